// round 1
// baseline (speedup 1.0000x reference)
#include <cuda_runtime.h>

#define B_    16
#define S_    10
#define D_    128
#define C_    256
#define NTOK  65536        /* B*H*W tokens total */
#define NPB   4096         /* tokens per batch   */
#define HID_  256
#define T_    20
#define CHUNK 128
#define NCHUNK 32          /* NPB / CHUNK */

// ---- scratch (device globals; no allocations allowed) ----
__device__ float g_k[NTOK * D_];                 // 33.5 MB
__device__ float g_v[NTOK * D_];                 // 33.5 MB
__device__ float g_slots[B_ * S_ * D_];
__device__ float g_q[B_ * S_ * D_];
__device__ float g_pnum[(size_t)B_ * NCHUNK * S_ * D_];
__device__ float g_pden[B_ * NCHUNK * S_];

__device__ __forceinline__ float2 warpRed2(float a, float b) {
    #pragma unroll
    for (int o = 16; o > 0; o >>= 1) {
        a += __shfl_xor_sync(0xffffffffu, a, o);
        b += __shfl_xor_sync(0xffffffffu, b, o);
    }
    return make_float2(a, b);
}

// ============================================================================
// Kernel 1: fused LayerNorm(obs) + K,V projection GEMM.
// 64 tokens per block, 256 threads. Packed f32x2 FMA (2 FLOP/issue slot).
// Micro-tile per thread: 8 tokens x 4 d-cols x {k,v}.
// ============================================================================
__global__ __launch_bounds__(256, 2) void k_ln_kv(
    const float* __restrict__ obs, const float* __restrict__ niw,
    const float* __restrict__ nib, const float* __restrict__ Wk,
    const float* __restrict__ Wv)
{
    extern __shared__ float sm[];
    float* xs  = sm;                // [64][256] normalized x tile
    float* wks = sm + 64 * 256;     // [32][128] Wk chunk
    float* wvs = wks + 32 * 128;    // [32][128] Wv chunk

    const int tid  = threadIdx.x;
    const int wid  = tid >> 5;
    const int lane = tid & 31;
    const int t0   = blockIdx.x * 64;

    // per-lane LN params (columns 4*lane.. and +128)
    const int c0 = lane * 4;
    float4 nw0 = *(const float4*)(niw + c0);
    float4 nw1 = *(const float4*)(niw + c0 + 128);
    float4 nb0 = *(const float4*)(nib + c0);
    float4 nb1 = *(const float4*)(nib + c0 + 128);

    // ---- load + LayerNorm: warp wid owns rows wid*8 .. wid*8+7 ----
    #pragma unroll
    for (int i = 0; i < 8; i++) {
        int r = wid * 8 + i;
        const float4* src = (const float4*)(obs + (size_t)(t0 + r) * C_);
        float4 v0 = src[lane];
        float4 v1 = src[lane + 32];
        float s  = v0.x + v0.y + v0.z + v0.w + v1.x + v1.y + v1.z + v1.w;
        float ss = v0.x*v0.x + v0.y*v0.y + v0.z*v0.z + v0.w*v0.w
                 + v1.x*v1.x + v1.y*v1.y + v1.z*v1.z + v1.w*v1.w;
        float2 red = warpRed2(s, ss);
        float mu  = red.x * (1.0f / 256.0f);
        float var = red.y * (1.0f / 256.0f) - mu * mu;
        float rsg = rsqrtf(var + 1e-5f);
        float* xr = xs + r * 256;
        xr[c0 + 0]   = (v0.x - mu) * rsg * nw0.x + nb0.x;
        xr[c0 + 1]   = (v0.y - mu) * rsg * nw0.y + nb0.y;
        xr[c0 + 2]   = (v0.z - mu) * rsg * nw0.z + nb0.z;
        xr[c0 + 3]   = (v0.w - mu) * rsg * nw0.w + nb0.w;
        xr[c0 + 128] = (v1.x - mu) * rsg * nw1.x + nb1.x;
        xr[c0 + 129] = (v1.y - mu) * rsg * nw1.y + nb1.y;
        xr[c0 + 130] = (v1.z - mu) * rsg * nw1.z + nb1.z;
        xr[c0 + 131] = (v1.w - mu) * rsg * nw1.w + nb1.w;
    }

    // ---- GEMM: [64 x 256] @ [256 x 128] for both K and V ----
    const int ty = wid;     // token group (8 tokens)
    const int tx = lane;    // d-col group (4 cols)
    unsigned long long ak[16], av[16];
    #pragma unroll
    for (int i = 0; i < 16; i++) { ak[i] = 0ULL; av[i] = 0ULL; }

    #pragma unroll 1
    for (int step = 0; step < 8; step++) {
        __syncthreads();
        #pragma unroll
        for (int i = 0; i < 4; i++) {
            int u = tid + i * 256;                        // float4 index in [0,1024)
            ((float4*)wks)[u] = ((const float4*)Wk)[step * 1024 + u];
            ((float4*)wvs)[u] = ((const float4*)Wv)[step * 1024 + u];
        }
        __syncthreads();
        const float* ar = xs + ty * 8 * 256 + step * 32;
        #pragma unroll 8
        for (int cc = 0; cc < 32; cc++) {
            unsigned long long bk0 = *(const unsigned long long*)(wks + cc * 128 + tx * 4);
            unsigned long long bk1 = *(const unsigned long long*)(wks + cc * 128 + tx * 4 + 2);
            unsigned long long bv0 = *(const unsigned long long*)(wvs + cc * 128 + tx * 4);
            unsigned long long bv1 = *(const unsigned long long*)(wvs + cc * 128 + tx * 4 + 2);
            #pragma unroll
            for (int i = 0; i < 8; i++) {
                unsigned int au = __float_as_uint(ar[i * 256 + cc]);
                unsigned long long a2;
                asm("mov.b64 %0, {%1, %1};" : "=l"(a2) : "r"(au));
                asm("fma.rn.f32x2 %0, %1, %2, %0;" : "+l"(ak[i*2+0]) : "l"(a2), "l"(bk0));
                asm("fma.rn.f32x2 %0, %1, %2, %0;" : "+l"(ak[i*2+1]) : "l"(a2), "l"(bk1));
                asm("fma.rn.f32x2 %0, %1, %2, %0;" : "+l"(av[i*2+0]) : "l"(a2), "l"(bv0));
                asm("fma.rn.f32x2 %0, %1, %2, %0;" : "+l"(av[i*2+1]) : "l"(a2), "l"(bv1));
            }
        }
    }

    #pragma unroll
    for (int i = 0; i < 8; i++) {
        int t = t0 + ty * 8 + i;
        float2 k0 = *(float2*)&ak[i*2 + 0];
        float2 k1 = *(float2*)&ak[i*2 + 1];
        float2 w0 = *(float2*)&av[i*2 + 0];
        float2 w1 = *(float2*)&av[i*2 + 1];
        *(float4*)(g_k + (size_t)t * D_ + tx * 4) = make_float4(k0.x, k0.y, k1.x, k1.y);
        *(float4*)(g_v + (size_t)t * D_ + tx * 4) = make_float4(w0.x, w0.y, w1.x, w1.y);
    }
}

// ============================================================================
// Kernel 2: slot init = mu + exp(log_sigma) * noise
// ============================================================================
__global__ void k_init(const float* __restrict__ noise, const float* __restrict__ mu,
                       const float* __restrict__ ls)
{
    int i = blockIdx.x * 256 + threadIdx.x;
    if (i < B_ * S_ * D_) {
        int d = i & (D_ - 1);
        g_slots[i] = mu[d] + expf(ls[d]) * noise[i];
    }
}

// ============================================================================
// Kernel 3a: q = (LN(slots) @ Wq) * scale.  One block per (b,s), 128 threads.
// ============================================================================
__global__ void k_q(const float* __restrict__ nsw, const float* __restrict__ nsb,
                    const float* __restrict__ Wq)
{
    __shared__ float h[128];
    __shared__ float r1[4], r2[4];
    const int bs = blockIdx.x;
    const int d  = threadIdx.x;
    float x = g_slots[bs * 128 + d];
    float2 red = warpRed2(x, x * x);
    int wid = d >> 5, lane = d & 31;
    if (lane == 0) { r1[wid] = red.x; r2[wid] = red.y; }
    __syncthreads();
    float Sm = r1[0] + r1[1] + r1[2] + r1[3];
    float Sq = r2[0] + r2[1] + r2[2] + r2[3];
    float mu  = Sm * (1.0f / 128.0f);
    float var = Sq * (1.0f / 128.0f) - mu * mu;
    float rs  = rsqrtf(var + 1e-5f);
    h[d] = (x - mu) * rs * nsw[d] + nsb[d];
    __syncthreads();
    float a0 = 0, a1 = 0, a2 = 0, a3 = 0;
    #pragma unroll
    for (int c = 0; c < 128; c += 4) {
        a0 += h[c + 0] * Wq[(c + 0) * 128 + d];
        a1 += h[c + 1] * Wq[(c + 1) * 128 + d];
        a2 += h[c + 2] * Wq[(c + 2) * 128 + d];
        a3 += h[c + 3] * Wq[(c + 3) * 128 + d];
    }
    g_q[bs * 128 + d] = (a0 + a1 + a2 + a3) * 0.08838834764831845f; // 1/sqrt(128)
}

// ============================================================================
// Kernel 3b: fused attention pass over one 128-token chunk:
//   logits -> softmax over slots -> partial (sum_n attn * v) and (sum_n attn)
// grid (NCHUNK, B_), 256 threads.
// ============================================================================
__global__ __launch_bounds__(256, 2) void k_attn()
{
    extern __shared__ float sm2[];
    float* tile  = sm2;                 // [128][129] K then V
    float* qs    = tile + 128 * 129;    // [10][128]
    float* attns = qs + 1280;           // [128][12]

    const int tid = threadIdx.x;
    const int ck  = blockIdx.x;
    const int b   = blockIdx.y;
    const int tokbase = b * NPB + ck * CHUNK;

    // load q
    #pragma unroll
    for (int i = 0; i < 5; i++) {
        int idx = tid + i * 256;
        qs[idx] = g_q[b * S_ * D_ + idx];
    }
    // load K tile
    {
        const float4* src = (const float4*)(g_k + (size_t)tokbase * D_);
        #pragma unroll
        for (int i = 0; i < 16; i++) {
            int u = tid + i * 256;
            int r = u >> 5, c4 = u & 31;
            float4 val = src[u];
            float* dst = tile + r * 129 + c4 * 4;
            dst[0] = val.x; dst[1] = val.y; dst[2] = val.z; dst[3] = val.w;
        }
    }
    __syncthreads();

    // logits: thread covers token t, slots {s0, s0+2, s0+4, s0+6, s0+8}
    const int t  = tid & 127;
    const int s0 = tid >> 7;
    {
        float lg0 = 0, lg1 = 0, lg2 = 0, lg3 = 0, lg4 = 0;
        const float* kr = tile + t * 129;
        const float* qb = qs + s0 * 128;
        #pragma unroll 4
        for (int dd = 0; dd < 128; dd++) {
            float kv = kr[dd];
            lg0 += kv * qb[dd];
            lg1 += kv * qb[dd + 256];
            lg2 += kv * qb[dd + 512];
            lg3 += kv * qb[dd + 768];
            lg4 += kv * qb[dd + 1024];
        }
        attns[t * 12 + s0 + 0] = lg0;
        attns[t * 12 + s0 + 2] = lg1;
        attns[t * 12 + s0 + 4] = lg2;
        attns[t * 12 + s0 + 6] = lg3;
        attns[t * 12 + s0 + 8] = lg4;
    }
    __syncthreads();

    // softmax over the 10 slots, per token
    if (tid < 128) {
        float v[10]; float m = -1e30f;
        #pragma unroll
        for (int s = 0; s < 10; s++) { v[s] = attns[tid * 12 + s]; m = fmaxf(m, v[s]); }
        float sum = 0.f;
        #pragma unroll
        for (int s = 0; s < 10; s++) { v[s] = __expf(v[s] - m); sum += v[s]; }
        float inv = 1.0f / sum;
        #pragma unroll
        for (int s = 0; s < 10; s++) attns[tid * 12 + s] = v[s] * inv;
    }
    __syncthreads();

    // per-slot denominators + load V tile (independent, same phase)
    {
        int wid = tid >> 5, lane = tid & 31;
        for (int s = wid; s < 10; s += 8) {
            float p = attns[lane * 12 + s] + attns[(lane + 32) * 12 + s]
                    + attns[(lane + 64) * 12 + s] + attns[(lane + 96) * 12 + s];
            #pragma unroll
            for (int o = 16; o > 0; o >>= 1) p += __shfl_xor_sync(0xffffffffu, p, o);
            if (lane == 0) g_pden[(b * NCHUNK + ck) * S_ + s] = p;
        }
        const float4* src = (const float4*)(g_v + (size_t)tokbase * D_);
        #pragma unroll
        for (int i = 0; i < 16; i++) {
            int u = tid + i * 256;
            int r = u >> 5, c4 = u & 31;
            float4 val = src[u];
            float* dst = tile + r * 129 + c4 * 4;
            dst[0] = val.x; dst[1] = val.y; dst[2] = val.z; dst[3] = val.w;
        }
    }
    __syncthreads();

    // partial numerators: numer[s][d] = sum_t attn[t][s] * v[t][d]
    {
        const int d = tid & 127;
        const int g = tid >> 7;            // slot group: s = g*5 + j
        float a0 = 0, a1 = 0, a2 = 0, a3 = 0, a4 = 0;
        #pragma unroll 4
        for (int tt = 0; tt < 128; tt++) {
            float vv = tile[tt * 129 + d];
            const float* arow = attns + tt * 12 + g * 5;
            a0 += arow[0] * vv;
            a1 += arow[1] * vv;
            a2 += arow[2] * vv;
            a3 += arow[3] * vv;
            a4 += arow[4] * vv;
        }
        float* dst = g_pnum + ((size_t)(b * NCHUNK + ck) * S_ + g * 5) * D_ + d;
        dst[0 * D_] = a0;
        dst[1 * D_] = a1;
        dst[2 * D_] = a2;
        dst[3 * D_] = a3;
        dst[4 * D_] = a4;
    }
}

// ============================================================================
// Kernel 3c: reduce chunk partials, slot residual update, LN + MLP residual.
// One block per (b,s), 256 threads.
// ============================================================================
__global__ void k_upd(const float* __restrict__ nmw, const float* __restrict__ nmb,
                      const float* __restrict__ w1, const float* __restrict__ b1,
                      const float* __restrict__ w2, const float* __restrict__ b2)
{
    __shared__ float hm[128];
    __shared__ float hid[256];
    __shared__ float r1[8], r2[8];
    __shared__ float sden;
    const int tid = threadIdx.x;
    const int b = blockIdx.x / 10;
    const int s = blockIdx.x % 10;

    // denominator: warp 4 reduces the 32 chunk partials
    if ((tid >> 5) == 4) {
        int lane = tid & 31;
        float p = g_pden[(b * NCHUNK + lane) * S_ + s];
        #pragma unroll
        for (int o = 16; o > 0; o >>= 1) p += __shfl_xor_sync(0xffffffffu, p, o);
        if (lane == 0) sden = p;
    }
    float upd = 0.f;
    if (tid < 128) {
        #pragma unroll 8
        for (int ch = 0; ch < NCHUNK; ch++)
            upd += g_pnum[((size_t)(b * NCHUNK + ch) * S_ + s) * D_ + tid];
    }
    __syncthreads();

    float slot_new = 0.f;
    float sS = 0.f, sQ = 0.f;
    if (tid < 128) {
        slot_new = g_slots[(b * S_ + s) * D_ + tid] + upd / (sden + 1e-8f);
        sS = slot_new; sQ = slot_new * slot_new;
    }
    float2 red = warpRed2(sS, sQ);
    int wid = tid >> 5, lane = tid & 31;
    if (lane == 0) { r1[wid] = red.x; r2[wid] = red.y; }
    __syncthreads();
    float Sm = 0.f, Sq = 0.f;
    #pragma unroll
    for (int i = 0; i < 8; i++) { Sm += r1[i]; Sq += r2[i]; }
    float mu  = Sm * (1.0f / 128.0f);
    float var = Sq * (1.0f / 128.0f) - mu * mu;
    float rs  = rsqrtf(var + 1e-5f);
    if (tid < 128) hm[tid] = (slot_new - mu) * rs * nmw[tid] + nmb[tid];
    __syncthreads();

    float acc = b1[tid];
    #pragma unroll 4
    for (int c = 0; c < 128; c++) acc += hm[c] * w1[c * 256 + tid];
    hid[tid] = fmaxf(acc, 0.f);
    __syncthreads();

    if (tid < 128) {
        float o = b2[tid];
        #pragma unroll 4
        for (int j = 0; j < 256; j++) o += hid[j] * w2[j * 128 + tid];
        g_slots[(b * S_ + s) * D_ + tid] = slot_new + o;
    }
}

// ============================================================================
// Kernel 4: heads. objects = relu(slots@pd_w1+b1)@pd_w2+b2, types = slots@tc_w+tc_b
// ============================================================================
__global__ void k_heads(const float* __restrict__ w1, const float* __restrict__ b1,
                        const float* __restrict__ w2, const float* __restrict__ b2,
                        const float* __restrict__ tw, const float* __restrict__ tb,
                        float* __restrict__ out)
{
    __shared__ float sl[128];
    __shared__ float hid[256];
    const int tid = threadIdx.x;
    const int bs  = blockIdx.x;
    if (tid < 128) sl[tid] = g_slots[bs * 128 + tid];
    __syncthreads();
    float acc = b1[tid];
    #pragma unroll 4
    for (int c = 0; c < 128; c++) acc += sl[c] * w1[c * 256 + tid];
    hid[tid] = fmaxf(acc, 0.f);
    __syncthreads();
    if (tid < 128) {
        float o = b2[tid];
        #pragma unroll 4
        for (int j = 0; j < 256; j++) o += hid[j] * w2[j * 128 + tid];
        out[bs * 128 + tid] = o;
    } else if (tid < 128 + T_) {
        int tt = tid - 128;
        float o = tb[tt];
        #pragma unroll 4
        for (int c = 0; c < 128; c++) o += sl[c] * tw[c * T_ + tt];
        out[B_ * S_ * D_ + bs * T_ + tt] = o;
    }
}

// ============================================================================
extern "C" void kernel_launch(void* const* d_in, const int* in_sizes, int n_in,
                              void* d_out, int out_size)
{
    const float* obs  = (const float*)d_in[0];
    const float* noise= (const float*)d_in[1];
    const float* smu  = (const float*)d_in[2];
    const float* sls  = (const float*)d_in[3];
    const float* niw  = (const float*)d_in[4];
    const float* nib  = (const float*)d_in[5];
    const float* nsw  = (const float*)d_in[6];
    const float* nsb  = (const float*)d_in[7];
    const float* nmw  = (const float*)d_in[8];
    const float* nmb  = (const float*)d_in[9];
    const float* Wq   = (const float*)d_in[10];
    const float* Wk   = (const float*)d_in[11];
    const float* Wv   = (const float*)d_in[12];
    const float* mw1  = (const float*)d_in[13];
    const float* mb1  = (const float*)d_in[14];
    const float* mw2  = (const float*)d_in[15];
    const float* mb2  = (const float*)d_in[16];
    const float* pw1  = (const float*)d_in[17];
    const float* pb1  = (const float*)d_in[18];
    const float* pw2  = (const float*)d_in[19];
    const float* pb2  = (const float*)d_in[20];
    const float* tcw  = (const float*)d_in[21];
    const float* tcb  = (const float*)d_in[22];
    float* out = (float*)d_out;

    const int SMEM1 = (64 * 256 + 2 * 32 * 128) * 4;           // 98304 B
    const int SMEM2 = (128 * 129 + 1280 + 128 * 12) * 4;       // 77312 B
    cudaFuncSetAttribute(k_ln_kv, cudaFuncAttributeMaxDynamicSharedMemorySize, SMEM1);
    cudaFuncSetAttribute(k_attn,  cudaFuncAttributeMaxDynamicSharedMemorySize, SMEM2);

    k_ln_kv<<<NTOK / 64, 256, SMEM1>>>(obs, niw, nib, Wk, Wv);
    k_init<<<(B_ * S_ * D_ + 255) / 256, 256>>>(noise, smu, sls);
    for (int it = 0; it < 3; it++) {
        k_q<<<B_ * S_, 128>>>(nsw, nsb, Wq);
        dim3 g2(NCHUNK, B_);
        k_attn<<<g2, 256, SMEM2>>>();
        k_upd<<<B_ * S_, 256>>>(nmw, nmb, mw1, mb1, mw2, mb2);
    }
    k_heads<<<B_ * S_, 256>>>(pw1, pb1, pw2, pb2, tcw, tcb, out);
}

// round 2
// speedup vs baseline: 1.5640x; 1.5640x over previous
#include <cuda_runtime.h>
#include <cuda_bf16.h>
#include <cstdint>

#define B_    16
#define S_    10
#define D_    128
#define C_    256
#define NTOK  65536        /* B*H*W tokens total */
#define NPB   4096         /* tokens per batch   */
#define HID_  256
#define T_    20
#define CHUNK 128
#define NCHUNK 32          /* NPB / CHUNK */

// ---- scratch (device globals; no allocations allowed) ----
__device__ __nv_bfloat16 g_k[NTOK * D_];     // 16.8 MB
__device__ __nv_bfloat16 g_v[NTOK * D_];     // 16.8 MB
__device__ __nv_bfloat16 g_wkT[D_ * C_];     // Wk^T [d][c] bf16
__device__ __nv_bfloat16 g_wvT[D_ * C_];     // Wv^T [d][c] bf16
__device__ float g_slots[B_ * S_ * D_];
__device__ float g_q[B_ * S_ * D_];
__device__ float g_pnum[(size_t)B_ * NCHUNK * S_ * D_];
__device__ float g_pden[B_ * NCHUNK * S_];

__device__ __forceinline__ float2 warpRed2(float a, float b) {
    #pragma unroll
    for (int o = 16; o > 0; o >>= 1) {
        a += __shfl_xor_sync(0xffffffffu, a, o);
        b += __shfl_xor_sync(0xffffffffu, b, o);
    }
    return make_float2(a, b);
}

__device__ __forceinline__ uint32_t s2u(const void* p) {
    return (uint32_t)__cvta_generic_to_shared(p);
}

#define LDSM4(r, addr)                                                          \
    asm volatile("ldmatrix.sync.aligned.m8n8.x4.shared.b16 {%0,%1,%2,%3}, [%4];"\
                 : "=r"((r)[0]), "=r"((r)[1]), "=r"((r)[2]), "=r"((r)[3])       \
                 : "r"(addr))

#define MMA_BF16(d, a, b0, b1)                                                  \
    asm volatile("mma.sync.aligned.m16n8k16.row.col.f32.bf16.bf16.f32 "         \
                 "{%0,%1,%2,%3}, {%4,%5,%6,%7}, {%8,%9}, {%0,%1,%2,%3};"        \
                 : "+f"((d)[0]), "+f"((d)[1]), "+f"((d)[2]), "+f"((d)[3])       \
                 : "r"((a)[0]), "r"((a)[1]), "r"((a)[2]), "r"((a)[3]),          \
                   "r"(b0), "r"(b1))

// ============================================================================
// Kernel 0: one-time weight transpose + bf16 convert.  g_wT[d][c] = W[c][d].
// ============================================================================
__global__ void k_prep(const float* __restrict__ Wk, const float* __restrict__ Wv)
{
    int d = blockIdx.x;     // 128
    int c = threadIdx.x;    // 256
    g_wkT[d * C_ + c] = __float2bfloat16(Wk[c * D_ + d]);
    g_wvT[d * C_ + c] = __float2bfloat16(Wv[c * D_ + d]);
}

// ============================================================================
// Kernel 1: fused LayerNorm(obs) + K,V projection via bf16 tensor-core MMA.
// 128 tokens/block, 512 threads (16 warps).  Warps 0-7 -> K, 8-15 -> V;
// each warp computes a 32(m) x 64(n) tile with mma.m16n8k16.
// smem (bf16, row stride 264): xs[128][264], wk[128][264], wv[128][264].
// ============================================================================
#define XSTRIDE 264
__global__ __launch_bounds__(512, 1) void k_ln_kv(
    const float* __restrict__ obs, const float* __restrict__ niw,
    const float* __restrict__ nib)
{
    extern __shared__ char smx[];
    __nv_bfloat16* xs  = (__nv_bfloat16*)smx;           // [128][264]
    __nv_bfloat16* wks = xs + 128 * XSTRIDE;
    __nv_bfloat16* wvs = wks + 128 * XSTRIDE;

    const int tid  = threadIdx.x;
    const int wid  = tid >> 5;
    const int lane = tid & 31;
    const int t0   = blockIdx.x * 128;

    // ---- stage bf16 transposed weights: [128 d][256 c] -> stride-264 smem ----
    {
        const uint4* gk4 = (const uint4*)g_wkT;   // 4096 uint4
        const uint4* gv4 = (const uint4*)g_wvT;
        #pragma unroll
        for (int i = 0; i < 8; i++) {
            int u = tid + i * 512;
            int row = u >> 5, c = u & 31;
            *(uint4*)((char*)wks + row * (XSTRIDE * 2) + c * 16) = gk4[u];
            *(uint4*)((char*)wvs + row * (XSTRIDE * 2) + c * 16) = gv4[u];
        }
    }

    // ---- LayerNorm: warp owns 8 rows ----
    {
        const int c0 = lane * 4;
        float4 nw0 = *(const float4*)(niw + c0);
        float4 nw1 = *(const float4*)(niw + c0 + 128);
        float4 nb0 = *(const float4*)(nib + c0);
        float4 nb1 = *(const float4*)(nib + c0 + 128);
        #pragma unroll
        for (int i = 0; i < 8; i++) {
            int r = wid * 8 + i;
            const float4* src = (const float4*)(obs + (size_t)(t0 + r) * C_);
            float4 v0 = src[lane];
            float4 v1 = src[lane + 32];
            float s  = v0.x + v0.y + v0.z + v0.w + v1.x + v1.y + v1.z + v1.w;
            float ss = v0.x*v0.x + v0.y*v0.y + v0.z*v0.z + v0.w*v0.w
                     + v1.x*v1.x + v1.y*v1.y + v1.z*v1.z + v1.w*v1.w;
            float2 red = warpRed2(s, ss);
            float mu  = red.x * (1.0f / 256.0f);
            float var = red.y * (1.0f / 256.0f) - mu * mu;
            float rsg = rsqrtf(var + 1e-5f);
            char* xr = (char*)xs + r * (XSTRIDE * 2);
            *(__nv_bfloat162*)(xr + (c0 + 0) * 2) =
                __floats2bfloat162_rn((v0.x - mu) * rsg * nw0.x + nb0.x,
                                      (v0.y - mu) * rsg * nw0.y + nb0.y);
            *(__nv_bfloat162*)(xr + (c0 + 2) * 2) =
                __floats2bfloat162_rn((v0.z - mu) * rsg * nw0.z + nb0.z,
                                      (v0.w - mu) * rsg * nw0.w + nb0.w);
            *(__nv_bfloat162*)(xr + (c0 + 128) * 2) =
                __floats2bfloat162_rn((v1.x - mu) * rsg * nw1.x + nb1.x,
                                      (v1.y - mu) * rsg * nw1.y + nb1.y);
            *(__nv_bfloat162*)(xr + (c0 + 130) * 2) =
                __floats2bfloat162_rn((v1.z - mu) * rsg * nw1.z + nb1.z,
                                      (v1.w - mu) * rsg * nw1.w + nb1.w);
        }
    }
    __syncthreads();

    // ---- MMA mainloop ----
    const int mat = wid >> 3;          // 0 = K, 1 = V
    const int wm  = wid & 3;           // m-block (32 rows)
    const int wn  = (wid >> 2) & 1;    // n-half (64 cols)
    const __nv_bfloat16* wsm = mat ? wvs : wks;

    const int ga = lane >> 3, ra = lane & 7;
    uint32_t aA = s2u(xs) +
        (uint32_t)(((wm * 32 + ra + ((ga & 1) << 3)) * XSTRIDE + ((ga >> 1) << 3)) * 2);
    uint32_t aB = s2u(wsm) +
        (uint32_t)(((wn * 64 + ra + ((ga >> 1) << 3)) * XSTRIDE + ((ga & 1) << 3)) * 2);

    float acc[2][8][4];
    #pragma unroll
    for (int mi = 0; mi < 2; mi++)
        #pragma unroll
        for (int nj = 0; nj < 8; nj++)
            #pragma unroll
            for (int e = 0; e < 4; e++) acc[mi][nj][e] = 0.f;

    #pragma unroll 1
    for (int s = 0; s < 16; s++) {
        uint32_t A0[4], A1[4], Bx[4][4];
        LDSM4(A0, aA);
        LDSM4(A1, aA + 16 * (XSTRIDE * 2));
        #pragma unroll
        for (int j = 0; j < 4; j++)
            LDSM4(Bx[j], aB + j * 16 * (XSTRIDE * 2));
        #pragma unroll
        for (int nj = 0; nj < 8; nj++) {
            uint32_t b0 = Bx[nj >> 1][(nj & 1) * 2];
            uint32_t b1 = Bx[nj >> 1][(nj & 1) * 2 + 1];
            MMA_BF16(acc[0][nj], A0, b0, b1);
            MMA_BF16(acc[1][nj], A1, b0, b1);
        }
        aA += 32;   // 16 bf16 = 32 bytes per k-step
        aB += 32;
    }

    // ---- epilogue: D frag -> bf16 global [token][d] ----
    __nv_bfloat16* gout = mat ? g_v : g_k;
    const int qrow = lane >> 2;
    const int qcol = (lane & 3) * 2;
    const int rbase = t0 + wm * 32;
    #pragma unroll
    for (int mi = 0; mi < 2; mi++) {
        #pragma unroll
        for (int nj = 0; nj < 8; nj++) {
            int c  = wn * 64 + nj * 8 + qcol;
            int r0 = rbase + mi * 16 + qrow;
            *(__nv_bfloat162*)(gout + (size_t)r0 * D_ + c) =
                __floats2bfloat162_rn(acc[mi][nj][0], acc[mi][nj][1]);
            *(__nv_bfloat162*)(gout + (size_t)(r0 + 8) * D_ + c) =
                __floats2bfloat162_rn(acc[mi][nj][2], acc[mi][nj][3]);
        }
    }
}

// ============================================================================
// Kernel 2: slot init = mu + exp(log_sigma) * noise
// ============================================================================
__global__ void k_init(const float* __restrict__ noise, const float* __restrict__ mu,
                       const float* __restrict__ ls)
{
    int i = blockIdx.x * 256 + threadIdx.x;
    if (i < B_ * S_ * D_) {
        int d = i & (D_ - 1);
        g_slots[i] = mu[d] + expf(ls[d]) * noise[i];
    }
}

// ============================================================================
// Kernel 3a: q = (LN(slots) @ Wq) * scale.  One block per (b,s), 128 threads.
// ============================================================================
__global__ void k_q(const float* __restrict__ nsw, const float* __restrict__ nsb,
                    const float* __restrict__ Wq)
{
    __shared__ float h[128];
    __shared__ float r1[4], r2[4];
    const int bs = blockIdx.x;
    const int d  = threadIdx.x;
    float x = g_slots[bs * 128 + d];
    float2 red = warpRed2(x, x * x);
    int wid = d >> 5, lane = d & 31;
    if (lane == 0) { r1[wid] = red.x; r2[wid] = red.y; }
    __syncthreads();
    float Sm = r1[0] + r1[1] + r1[2] + r1[3];
    float Sq = r2[0] + r2[1] + r2[2] + r2[3];
    float mu  = Sm * (1.0f / 128.0f);
    float var = Sq * (1.0f / 128.0f) - mu * mu;
    float rs  = rsqrtf(var + 1e-5f);
    h[d] = (x - mu) * rs * nsw[d] + nsb[d];
    __syncthreads();
    float a0 = 0, a1 = 0, a2 = 0, a3 = 0;
    #pragma unroll
    for (int c = 0; c < 128; c += 4) {
        a0 += h[c + 0] * Wq[(c + 0) * 128 + d];
        a1 += h[c + 1] * Wq[(c + 1) * 128 + d];
        a2 += h[c + 2] * Wq[(c + 2) * 128 + d];
        a3 += h[c + 3] * Wq[(c + 3) * 128 + d];
    }
    g_q[bs * 128 + d] = (a0 + a1 + a2 + a3) * 0.08838834764831845f; // 1/sqrt(128)
}

// ============================================================================
// Kernel 3b: fused attention pass over one 128-token chunk (bf16 K/V tiles):
//   logits -> softmax over slots -> partial (sum_n attn * v) and (sum_n attn)
// grid (NCHUNK, B_), 256 threads, 4 CTAs/SM.
// tile stride 130 bf16 = 65 words (odd) -> conflict-free column reads.
// ============================================================================
#define TSTR 130
#define ATT_SMEM (128 * TSTR * 2 + 1280 * 4 + 128 * 12 * 4)
__global__ __launch_bounds__(256, 4) void k_attn()
{
    extern __shared__ char sm2[];
    __nv_bfloat16* tile = (__nv_bfloat16*)sm2;             // [128][130]
    float* qs    = (float*)(sm2 + 128 * TSTR * 2);         // [10][128]
    float* attns = qs + 1280;                              // [128][12]

    const int tid = threadIdx.x;
    const int ck  = blockIdx.x;
    const int b   = blockIdx.y;
    const int tokbase = b * NPB + ck * CHUNK;

    // load q
    #pragma unroll
    for (int i = 0; i < 5; i++) {
        int idx = tid + i * 256;
        qs[idx] = g_q[b * S_ * D_ + idx];
    }
    // load K tile (bf16): 2048 uint4 -> stride-65-word rows
    {
        const uint4* src = (const uint4*)(g_k + (size_t)tokbase * D_);
        uint32_t* tw = (uint32_t*)tile;
        #pragma unroll
        for (int i = 0; i < 8; i++) {
            int u = tid + i * 256;
            int row = u >> 4, c16 = u & 15;
            uint4 val = src[u];
            uint32_t* dst = tw + row * 65 + c16 * 4;
            dst[0] = val.x; dst[1] = val.y; dst[2] = val.z; dst[3] = val.w;
        }
    }
    __syncthreads();

    // logits: thread covers token t, slots {s0, s0+2, s0+4, s0+6, s0+8}
    const int t  = tid & 127;
    const int s0 = tid >> 7;
    {
        const uint32_t* kr = (const uint32_t*)tile + t * 65;
        const float2* qb = (const float2*)(qs + s0 * 128);
        float l0 = 0, l1 = 0, l2 = 0, l3 = 0, l4 = 0;
        #pragma unroll 4
        for (int p = 0; p < 64; p++) {
            float2 kv = __bfloat1622float2(*(const __nv_bfloat162*)(kr + p));
            float2 q0 = qb[p];
            float2 q1 = qb[p + 128];
            float2 q2 = qb[p + 256];
            float2 q3 = qb[p + 384];
            float2 q4 = qb[p + 512];
            l0 += kv.x * q0.x + kv.y * q0.y;
            l1 += kv.x * q1.x + kv.y * q1.y;
            l2 += kv.x * q2.x + kv.y * q2.y;
            l3 += kv.x * q3.x + kv.y * q3.y;
            l4 += kv.x * q4.x + kv.y * q4.y;
        }
        attns[t * 12 + s0 + 0] = l0;
        attns[t * 12 + s0 + 2] = l1;
        attns[t * 12 + s0 + 4] = l2;
        attns[t * 12 + s0 + 6] = l3;
        attns[t * 12 + s0 + 8] = l4;
    }
    __syncthreads();

    // softmax over the 10 slots, per token
    if (tid < 128) {
        float v[10]; float m = -1e30f;
        #pragma unroll
        for (int s = 0; s < 10; s++) { v[s] = attns[tid * 12 + s]; m = fmaxf(m, v[s]); }
        float sum = 0.f;
        #pragma unroll
        for (int s = 0; s < 10; s++) { v[s] = __expf(v[s] - m); sum += v[s]; }
        float inv = 1.0f / sum;
        #pragma unroll
        for (int s = 0; s < 10; s++) attns[tid * 12 + s] = v[s] * inv;
    }
    __syncthreads();

    // per-slot denominators + load V tile (independent, same phase)
    {
        int wid = tid >> 5, lane = tid & 31;
        for (int s = wid; s < 10; s += 8) {
            float p = attns[lane * 12 + s] + attns[(lane + 32) * 12 + s]
                    + attns[(lane + 64) * 12 + s] + attns[(lane + 96) * 12 + s];
            #pragma unroll
            for (int o = 16; o > 0; o >>= 1) p += __shfl_xor_sync(0xffffffffu, p, o);
            if (lane == 0) g_pden[(b * NCHUNK + ck) * S_ + s] = p;
        }
        const uint4* src = (const uint4*)(g_v + (size_t)tokbase * D_);
        uint32_t* tw = (uint32_t*)tile;
        #pragma unroll
        for (int i = 0; i < 8; i++) {
            int u = tid + i * 256;
            int row = u >> 4, c16 = u & 15;
            uint4 val = src[u];
            uint32_t* dst = tw + row * 65 + c16 * 4;
            dst[0] = val.x; dst[1] = val.y; dst[2] = val.z; dst[3] = val.w;
        }
    }
    __syncthreads();

    // partial numerators: numer[s][d] = sum_t attn[t][s] * v[t][d]
    {
        const int d = tid & 127;
        const int g = tid >> 7;            // slot group: s = g*5 + j
        const __nv_bfloat16* vcol = tile + d;
        const float* ar = attns + g * 5;
        float a0 = 0, a1 = 0, a2 = 0, a3 = 0, a4 = 0;
        #pragma unroll 4
        for (int tt = 0; tt < 128; tt++) {
            float vv = __bfloat162float(vcol[tt * TSTR]);
            const float* arr = ar + tt * 12;
            a0 += arr[0] * vv;
            a1 += arr[1] * vv;
            a2 += arr[2] * vv;
            a3 += arr[3] * vv;
            a4 += arr[4] * vv;
        }
        float* dst = g_pnum + ((size_t)(b * NCHUNK + ck) * S_ + g * 5) * D_ + d;
        dst[0 * D_] = a0;
        dst[1 * D_] = a1;
        dst[2 * D_] = a2;
        dst[3 * D_] = a3;
        dst[4 * D_] = a4;
    }
}

// ============================================================================
// Kernel 3c: reduce chunk partials, slot residual update, LN + MLP residual.
// One block per (b,s), 256 threads.
// ============================================================================
__global__ void k_upd(const float* __restrict__ nmw, const float* __restrict__ nmb,
                      const float* __restrict__ w1, const float* __restrict__ b1,
                      const float* __restrict__ w2, const float* __restrict__ b2)
{
    __shared__ float hm[128];
    __shared__ float hid[256];
    __shared__ float r1[8], r2[8];
    __shared__ float sden;
    const int tid = threadIdx.x;
    const int b = blockIdx.x / 10;
    const int s = blockIdx.x % 10;

    // denominator: warp 4 reduces the 32 chunk partials
    if ((tid >> 5) == 4) {
        int lane = tid & 31;
        float p = g_pden[(b * NCHUNK + lane) * S_ + s];
        #pragma unroll
        for (int o = 16; o > 0; o >>= 1) p += __shfl_xor_sync(0xffffffffu, p, o);
        if (lane == 0) sden = p;
    }
    float upd = 0.f;
    if (tid < 128) {
        #pragma unroll 8
        for (int ch = 0; ch < NCHUNK; ch++)
            upd += g_pnum[((size_t)(b * NCHUNK + ch) * S_ + s) * D_ + tid];
    }
    __syncthreads();

    float slot_new = 0.f;
    float sS = 0.f, sQ = 0.f;
    if (tid < 128) {
        slot_new = g_slots[(b * S_ + s) * D_ + tid] + upd / (sden + 1e-8f);
        sS = slot_new; sQ = slot_new * slot_new;
    }
    float2 red = warpRed2(sS, sQ);
    int wid = tid >> 5, lane = tid & 31;
    if (lane == 0) { r1[wid] = red.x; r2[wid] = red.y; }
    __syncthreads();
    float Sm = 0.f, Sq = 0.f;
    #pragma unroll
    for (int i = 0; i < 8; i++) { Sm += r1[i]; Sq += r2[i]; }
    float mu  = Sm * (1.0f / 128.0f);
    float var = Sq * (1.0f / 128.0f) - mu * mu;
    float rs  = rsqrtf(var + 1e-5f);
    if (tid < 128) hm[tid] = (slot_new - mu) * rs * nmw[tid] + nmb[tid];
    __syncthreads();

    float acc = b1[tid];
    #pragma unroll 4
    for (int c = 0; c < 128; c++) acc += hm[c] * w1[c * 256 + tid];
    hid[tid] = fmaxf(acc, 0.f);
    __syncthreads();

    if (tid < 128) {
        float o = b2[tid];
        #pragma unroll 4
        for (int j = 0; j < 256; j++) o += hid[j] * w2[j * 128 + tid];
        g_slots[(b * S_ + s) * D_ + tid] = slot_new + o;
    }
}

// ============================================================================
// Kernel 4: heads. objects = relu(slots@pd_w1+b1)@pd_w2+b2, types = slots@tc_w+tc_b
// ============================================================================
__global__ void k_heads(const float* __restrict__ w1, const float* __restrict__ b1,
                        const float* __restrict__ w2, const float* __restrict__ b2,
                        const float* __restrict__ tw, const float* __restrict__ tb,
                        float* __restrict__ out)
{
    __shared__ float sl[128];
    __shared__ float hid[256];
    const int tid = threadIdx.x;
    const int bs  = blockIdx.x;
    if (tid < 128) sl[tid] = g_slots[bs * 128 + tid];
    __syncthreads();
    float acc = b1[tid];
    #pragma unroll 4
    for (int c = 0; c < 128; c++) acc += sl[c] * w1[c * 256 + tid];
    hid[tid] = fmaxf(acc, 0.f);
    __syncthreads();
    if (tid < 128) {
        float o = b2[tid];
        #pragma unroll 4
        for (int j = 0; j < 256; j++) o += hid[j] * w2[j * 128 + tid];
        out[bs * 128 + tid] = o;
    } else if (tid < 128 + T_) {
        int tt = tid - 128;
        float o = tb[tt];
        #pragma unroll 4
        for (int c = 0; c < 128; c++) o += sl[c] * tw[c * T_ + tt];
        out[B_ * S_ * D_ + bs * T_ + tt] = o;
    }
}

// ============================================================================
extern "C" void kernel_launch(void* const* d_in, const int* in_sizes, int n_in,
                              void* d_out, int out_size)
{
    const float* obs  = (const float*)d_in[0];
    const float* noise= (const float*)d_in[1];
    const float* smu  = (const float*)d_in[2];
    const float* sls  = (const float*)d_in[3];
    const float* niw  = (const float*)d_in[4];
    const float* nib  = (const float*)d_in[5];
    const float* nsw  = (const float*)d_in[6];
    const float* nsb  = (const float*)d_in[7];
    const float* nmw  = (const float*)d_in[8];
    const float* nmb  = (const float*)d_in[9];
    const float* Wq   = (const float*)d_in[10];
    const float* Wk   = (const float*)d_in[11];
    const float* Wv   = (const float*)d_in[12];
    const float* mw1  = (const float*)d_in[13];
    const float* mb1  = (const float*)d_in[14];
    const float* mw2  = (const float*)d_in[15];
    const float* mb2  = (const float*)d_in[16];
    const float* pw1  = (const float*)d_in[17];
    const float* pb1  = (const float*)d_in[18];
    const float* pw2  = (const float*)d_in[19];
    const float* pb2  = (const float*)d_in[20];
    const float* tcw  = (const float*)d_in[21];
    const float* tcb  = (const float*)d_in[22];
    float* out = (float*)d_out;

    const int SMEM1 = 3 * 128 * XSTRIDE * 2;               // 202752 B
    cudaFuncSetAttribute(k_ln_kv, cudaFuncAttributeMaxDynamicSharedMemorySize, SMEM1);
    cudaFuncSetAttribute(k_attn,  cudaFuncAttributeMaxDynamicSharedMemorySize, ATT_SMEM);

    k_prep<<<D_, C_>>>(Wk, Wv);
    k_ln_kv<<<NTOK / 128, 512, SMEM1>>>(obs, niw, nib);
    k_init<<<(B_ * S_ * D_ + 255) / 256, 256>>>(noise, smu, sls);
    for (int it = 0; it < 3; it++) {
        k_q<<<B_ * S_, 128>>>(nsw, nsb, Wq);
        dim3 g2(NCHUNK, B_);
        k_attn<<<g2, 256, ATT_SMEM>>>();
        k_upd<<<B_ * S_, 256>>>(nmw, nmb, mw1, mb1, mw2, mb2);
    }
    k_heads<<<B_ * S_, 256>>>(pw1, pb1, pw2, pb2, tcw, tcb, out);
}

// round 4
// speedup vs baseline: 1.9262x; 1.2316x over previous
#include <cuda_runtime.h>
#include <cuda_bf16.h>
#include <cstdint>

#define B_    16
#define S_    10
#define D_    128
#define C_    256
#define NTOK  65536
#define NPB   4096
#define T_    20
#define CHUNK 128
#define NCHUNK 32

// ---- scratch ----
__device__ __nv_bfloat16 g_k[NTOK * D_];          // [tok][d]
__device__ __nv_bfloat16 g_vT[NTOK * D_];         // [b][d][4096 tok]
__device__ __nv_bfloat16 g_wkT[D_ * C_];
__device__ __nv_bfloat16 g_wvT[D_ * C_];
__device__ __nv_bfloat16 g_qb[B_ * 16 * D_];      // [b][16 slots(pad)][d]
__device__ float g_slots[B_ * S_ * D_];
__device__ float g_pnum[(size_t)B_ * NCHUNK * S_ * D_];
__device__ float g_pden[B_ * NCHUNK * S_];

__device__ __forceinline__ float2 warpRed2(float a, float b) {
    #pragma unroll
    for (int o = 16; o > 0; o >>= 1) {
        a += __shfl_xor_sync(0xffffffffu, a, o);
        b += __shfl_xor_sync(0xffffffffu, b, o);
    }
    return make_float2(a, b);
}

__device__ __forceinline__ uint32_t s2u(const void* p) {
    return (uint32_t)__cvta_generic_to_shared(p);
}

#define LDSM4(r, addr)                                                          \
    asm volatile("ldmatrix.sync.aligned.m8n8.x4.shared.b16 {%0,%1,%2,%3}, [%4];"\
                 : "=r"((r)[0]), "=r"((r)[1]), "=r"((r)[2]), "=r"((r)[3])       \
                 : "r"(addr))

#define MMA_BF16(d, a, b0, b1)                                                  \
    asm volatile("mma.sync.aligned.m16n8k16.row.col.f32.bf16.bf16.f32 "         \
                 "{%0,%1,%2,%3}, {%4,%5,%6,%7}, {%8,%9}, {%0,%1,%2,%3};"        \
                 : "+f"((d)[0]), "+f"((d)[1]), "+f"((d)[2]), "+f"((d)[3])       \
                 : "r"((a)[0]), "r"((a)[1]), "r"((a)[2]), "r"((a)[3]),          \
                   "r"(b0), "r"(b1))

// ============================================================================
// Kernel 0: weight transpose + bf16 convert
// ============================================================================
__global__ void k_prep(const float* __restrict__ Wk, const float* __restrict__ Wv)
{
    int d = blockIdx.x;
    int c = threadIdx.x;
    g_wkT[d * C_ + c] = __float2bfloat16(Wk[c * D_ + d]);
    g_wvT[d * C_ + c] = __float2bfloat16(Wv[c * D_ + d]);
}

// ============================================================================
// Kernel 1: LN + K,V projection (bf16 MMA). 256 tokens/block (2 tiles reuse
// one weight staging), 512 threads. K stored [t][d]; V stored transposed
// [b][d][tok] for the attention numerator MMA.
// ============================================================================
#define XSTRIDE 264
__global__ __launch_bounds__(512, 1) void k_ln_kv(
    const float* __restrict__ obs, const float* __restrict__ niw,
    const float* __restrict__ nib)
{
    extern __shared__ char smx[];
    __nv_bfloat16* xs  = (__nv_bfloat16*)smx;           // [128][264]
    __nv_bfloat16* wks = xs + 128 * XSTRIDE;
    __nv_bfloat16* wvs = wks + 128 * XSTRIDE;

    const int tid  = threadIdx.x;
    const int wid  = tid >> 5;
    const int lane = tid & 31;
    const int tblk = blockIdx.x * 256;
    const int bb   = tblk >> 12;            // batch
    const int tl0  = tblk & 4095;

    // stage bf16 transposed weights
    {
        const uint4* gk4 = (const uint4*)g_wkT;
        const uint4* gv4 = (const uint4*)g_wvT;
        #pragma unroll
        for (int i = 0; i < 8; i++) {
            int u = tid + i * 512;
            int row = u >> 5, c = u & 31;
            *(uint4*)((char*)wks + row * (XSTRIDE * 2) + c * 16) = gk4[u];
            *(uint4*)((char*)wvs + row * (XSTRIDE * 2) + c * 16) = gv4[u];
        }
    }

    const int c0 = lane * 4;
    float4 nw0 = *(const float4*)(niw + c0);
    float4 nw1 = *(const float4*)(niw + c0 + 128);
    float4 nb0 = *(const float4*)(nib + c0);
    float4 nb1 = *(const float4*)(nib + c0 + 128);

    const int mat = wid >> 3;          // 0 = K, 1 = V
    const int wm  = wid & 3;
    const int wn  = (wid >> 2) & 1;
    const __nv_bfloat16* wsm = mat ? wvs : wks;
    const int ga = lane >> 3, ra = lane & 7;
    const uint32_t aA0 = s2u(xs) +
        (uint32_t)(((wm * 32 + ra + ((ga & 1) << 3)) * XSTRIDE + ((ga >> 1) << 3)) * 2);
    const uint32_t aB0 = s2u(wsm) +
        (uint32_t)(((wn * 64 + ra + ((ga >> 1) << 3)) * XSTRIDE + ((ga & 1) << 3)) * 2);
    const int qrow = lane >> 2;
    const int qcol = (lane & 3) * 2;

    #pragma unroll 1
    for (int tile = 0; tile < 2; tile++) {
        const int t0 = tblk + tile * 128;
        __syncthreads();
        // LayerNorm: warp owns 8 rows
        #pragma unroll
        for (int i = 0; i < 8; i++) {
            int r = wid * 8 + i;
            const float4* src = (const float4*)(obs + (size_t)(t0 + r) * C_);
            float4 v0 = src[lane];
            float4 v1 = src[lane + 32];
            float s  = v0.x + v0.y + v0.z + v0.w + v1.x + v1.y + v1.z + v1.w;
            float ss = v0.x*v0.x + v0.y*v0.y + v0.z*v0.z + v0.w*v0.w
                     + v1.x*v1.x + v1.y*v1.y + v1.z*v1.z + v1.w*v1.w;
            float2 red = warpRed2(s, ss);
            float mu  = red.x * (1.0f / 256.0f);
            float var = red.y * (1.0f / 256.0f) - mu * mu;
            float rsg = rsqrtf(var + 1e-5f);
            char* xr = (char*)xs + r * (XSTRIDE * 2);
            *(__nv_bfloat162*)(xr + (c0 + 0) * 2) =
                __floats2bfloat162_rn((v0.x - mu) * rsg * nw0.x + nb0.x,
                                      (v0.y - mu) * rsg * nw0.y + nb0.y);
            *(__nv_bfloat162*)(xr + (c0 + 2) * 2) =
                __floats2bfloat162_rn((v0.z - mu) * rsg * nw0.z + nb0.z,
                                      (v0.w - mu) * rsg * nw0.w + nb0.w);
            *(__nv_bfloat162*)(xr + (c0 + 128) * 2) =
                __floats2bfloat162_rn((v1.x - mu) * rsg * nw1.x + nb1.x,
                                      (v1.y - mu) * rsg * nw1.y + nb1.y);
            *(__nv_bfloat162*)(xr + (c0 + 130) * 2) =
                __floats2bfloat162_rn((v1.z - mu) * rsg * nw1.z + nb1.z,
                                      (v1.w - mu) * rsg * nw1.w + nb1.w);
        }
        __syncthreads();

        float acc[2][8][4];
        #pragma unroll
        for (int mi = 0; mi < 2; mi++)
            #pragma unroll
            for (int nj = 0; nj < 8; nj++)
                #pragma unroll
                for (int e = 0; e < 4; e++) acc[mi][nj][e] = 0.f;

        uint32_t aA = aA0, aB = aB0;
        #pragma unroll 1
        for (int s = 0; s < 16; s++) {
            uint32_t A0[4], A1[4], Bx[4][4];
            LDSM4(A0, aA);
            LDSM4(A1, aA + 16 * (XSTRIDE * 2));
            #pragma unroll
            for (int j = 0; j < 4; j++)
                LDSM4(Bx[j], aB + j * 16 * (XSTRIDE * 2));
            #pragma unroll
            for (int nj = 0; nj < 8; nj++) {
                uint32_t b0 = Bx[nj >> 1][(nj & 1) * 2];
                uint32_t b1 = Bx[nj >> 1][(nj & 1) * 2 + 1];
                MMA_BF16(acc[0][nj], A0, b0, b1);
                MMA_BF16(acc[1][nj], A1, b0, b1);
            }
            aA += 32;
            aB += 32;
        }

        if (mat == 0) {
            // K: [t][d]
            #pragma unroll
            for (int mi = 0; mi < 2; mi++) {
                #pragma unroll
                for (int nj = 0; nj < 8; nj++) {
                    int c  = wn * 64 + nj * 8 + qcol;
                    int r0 = t0 + wm * 32 + mi * 16 + qrow;
                    *(__nv_bfloat162*)(g_k + (size_t)r0 * D_ + c) =
                        __floats2bfloat162_rn(acc[mi][nj][0], acc[mi][nj][1]);
                    *(__nv_bfloat162*)(g_k + (size_t)(r0 + 8) * D_ + c) =
                        __floats2bfloat162_rn(acc[mi][nj][2], acc[mi][nj][3]);
                }
            }
        } else {
            // V transposed: g_vT[bb][d][tloc]
            __nv_bfloat16* gv = g_vT + (size_t)bb * D_ * NPB;
            #pragma unroll
            for (int mi = 0; mi < 2; mi++) {
                #pragma unroll
                for (int nj = 0; nj < 8; nj++) {
                    int c  = wn * 64 + nj * 8 + qcol;
                    int tl = tl0 + tile * 128 + wm * 32 + mi * 16 + qrow;
                    gv[(size_t)c * NPB + tl]           = __float2bfloat16(acc[mi][nj][0]);
                    gv[(size_t)(c + 1) * NPB + tl]     = __float2bfloat16(acc[mi][nj][1]);
                    gv[(size_t)c * NPB + tl + 8]       = __float2bfloat16(acc[mi][nj][2]);
                    gv[(size_t)(c + 1) * NPB + tl + 8] = __float2bfloat16(acc[mi][nj][3]);
                }
            }
        }
    }
}

// ============================================================================
// Kernel 2: slot init + zero q padding rows
// ============================================================================
__global__ void k_init(const float* __restrict__ noise, const float* __restrict__ mu,
                       const float* __restrict__ ls)
{
    int i = blockIdx.x * 256 + threadIdx.x;
    if (i < B_ * S_ * D_) {
        int d = i & (D_ - 1);
        g_slots[i] = mu[d] + expf(ls[d]) * noise[i];
    }
    if (i < B_ * 6 * D_) {           // zero g_qb rows 10..15
        int b = i / 768, r = i % 768;
        g_qb[b * 2048 + 1280 + r] = __float2bfloat16(0.f);
    }
}

// ============================================================================
// Kernel 3: fused attention chunk (all tensor-core):
//   logits MMA -> softmax over slots -> den + numerator MMA -> partials
// grid (NCHUNK, B_), 256 threads, 4 CTAs/SM. smem 52KB.
// ============================================================================
#define TS 136
#define LSTR 132
#define ATT_SMEM (128*TS*2 + 16*TS*2 + 16*TS*2 + 16*LSTR*4)
__global__ __launch_bounds__(256, 4) void k_attn()
{
    extern __shared__ char sm2[];
    __nv_bfloat16* tile = (__nv_bfloat16*)sm2;              // [128][136] K then V^T
    __nv_bfloat16* Qs   = tile + 128 * TS;                  // [16][136]
    __nv_bfloat16* aBm  = Qs + 16 * TS;                     // attn bf16 [16][136]
    float* Ls           = (float*)(aBm + 16 * TS);          // logits [16][132]

    const int tid  = threadIdx.x;
    const int w    = tid >> 5;
    const int lane = tid & 31;
    const int ck   = blockIdx.x;
    const int b    = blockIdx.y;

    // load Q [16][128] : 16 rows * 16 uint4 = 256 uint4  (FIXED: was tid<128)
    {
        int row = tid >> 4, c = tid & 15;
        *(uint4*)((char*)Qs + row * (TS * 2) + c * 16) =
            ((const uint4*)(g_qb + b * 2048))[tid];
    }
    // zero attn pad rows 10..15 (6 rows * 272B = 102 uint4)
    if (tid < 102) {
        *(uint4*)((char*)aBm + 10 * (TS * 2) + tid * 16) = make_uint4(0, 0, 0, 0);
    }
    // load K tile [128 tok][128 d]
    {
        const uint4* src = (const uint4*)(g_k + ((size_t)b * NPB + ck * CHUNK) * D_);
        #pragma unroll
        for (int i = 0; i < 8; i++) {
            int u = tid + i * 256;
            int row = u >> 4, c = u & 15;
            *(uint4*)((char*)tile + row * (TS * 2) + c * 16) = src[u];
        }
    }
    __syncthreads();

    const int ga = lane >> 3, ra = lane & 7;
    const int qrow = lane >> 2, qcol = (lane & 3) * 2;
    const uint32_t baseA_q = s2u(Qs) +
        (uint32_t)(((ra + ((ga & 1) << 3)) * TS + ((ga >> 1) << 3)) * 2);
    const uint32_t baseB_t = s2u(tile) +
        (uint32_t)(((w * 16 + ra + ((ga >> 1) << 3)) * TS + ((ga & 1) << 3)) * 2);

    // ---- logits MMA: l[s][t] ----
    {
        float lacc[2][4] = {{0,0,0,0},{0,0,0,0}};
        #pragma unroll
        for (int ks = 0; ks < 8; ks++) {
            uint32_t A[4], Bx[4];
            LDSM4(A, baseA_q + ks * 32);
            LDSM4(Bx, baseB_t + ks * 32);
            MMA_BF16(lacc[0], A, Bx[0], Bx[1]);
            MMA_BF16(lacc[1], A, Bx[2], Bx[3]);
        }
        #pragma unroll
        for (int nj = 0; nj < 2; nj++) {
            int t = w * 16 + nj * 8 + qcol;
            Ls[qrow * LSTR + t]           = lacc[nj][0];
            Ls[qrow * LSTR + t + 1]       = lacc[nj][1];
            Ls[(qrow + 8) * LSTR + t]     = lacc[nj][2];
            Ls[(qrow + 8) * LSTR + t + 1] = lacc[nj][3];
        }
    }
    __syncthreads();

    // ---- softmax over 10 slots per token, write bf16 attn ----
    if (tid < 128) {
        float v[10]; float m = -1e30f;
        #pragma unroll
        for (int s = 0; s < 10; s++) { v[s] = Ls[s * LSTR + tid]; m = fmaxf(m, v[s]); }
        float sum = 0.f;
        #pragma unroll
        for (int s = 0; s < 10; s++) { v[s] = __expf(v[s] - m); sum += v[s]; }
        float inv = 1.0f / sum;
        #pragma unroll
        for (int s = 0; s < 10; s++) aBm[s * TS + tid] = __float2bfloat16(v[s] * inv);
    }
    __syncthreads();

    // ---- denominators + load V^T tile ----
    for (int s = w; s < 10; s += 8) {
        float p = __bfloat162float(aBm[s * TS + lane])
                + __bfloat162float(aBm[s * TS + lane + 32])
                + __bfloat162float(aBm[s * TS + lane + 64])
                + __bfloat162float(aBm[s * TS + lane + 96]);
        #pragma unroll
        for (int o = 16; o > 0; o >>= 1) p += __shfl_xor_sync(0xffffffffu, p, o);
        if (lane == 0) g_pden[(b * NCHUNK + ck) * S_ + s] = p;
    }
    {
        const uint4* src = (const uint4*)(g_vT + (size_t)b * D_ * NPB);
        #pragma unroll
        for (int i = 0; i < 8; i++) {
            int u = tid + i * 256;
            int row = u >> 4, c = u & 15;        // row = d
            *(uint4*)((char*)tile + row * (TS * 2) + c * 16) =
                src[row * (NPB / 8) + ck * 16 + c];
        }
    }
    __syncthreads();

    // ---- numerator MMA: upd[s][d] = sum_t attn[s][t] * vT[d][t] ----
    {
        const uint32_t baseA_a = s2u(aBm) +
            (uint32_t)(((ra + ((ga & 1) << 3)) * TS + ((ga >> 1) << 3)) * 2);
        float nacc[2][4] = {{0,0,0,0},{0,0,0,0}};
        #pragma unroll
        for (int ks = 0; ks < 8; ks++) {
            uint32_t A[4], Bx[4];
            LDSM4(A, baseA_a + ks * 32);
            LDSM4(Bx, baseB_t + ks * 32);
            MMA_BF16(nacc[0], A, Bx[0], Bx[1]);
            MMA_BF16(nacc[1], A, Bx[2], Bx[3]);
        }
        float* dst = g_pnum + (size_t)(b * NCHUNK + ck) * S_ * D_;
        #pragma unroll
        for (int nj = 0; nj < 2; nj++) {
            int d = w * 16 + nj * 8 + qcol;
            *(float2*)(dst + qrow * D_ + d) = make_float2(nacc[nj][0], nacc[nj][1]);
            if (qrow + 8 < 10)
                *(float2*)(dst + (qrow + 8) * D_ + d) = make_float2(nacc[nj][2], nacc[nj][3]);
        }
    }
}

// ============================================================================
// 256-thread block reduction helper (mean/var over 128 values)
// ============================================================================
__device__ __forceinline__ void ln_stats(float x, float* r1, float* r2,
                                         float& mu, float& rs) {
    float2 red = warpRed2(x, x * x);
    int wid = threadIdx.x >> 5, lane = threadIdx.x & 31;
    if (lane == 0) { r1[wid] = red.x; r2[wid] = red.y; }
    __syncthreads();
    float Sm = 0.f, Sq = 0.f;
    #pragma unroll
    for (int i = 0; i < 8; i++) { Sm += r1[i]; Sq += r2[i]; }
    mu = Sm * (1.0f / 128.0f);
    float var = Sq * (1.0f / 128.0f) - mu * mu;
    rs = rsqrtf(var + 1e-5f);
}

// ============================================================================
// Kernel 4: fused slot update (optional) + q projection.  grid 160, 256 thr.
// ============================================================================
__global__ void k_slotq(const float* __restrict__ nmw, const float* __restrict__ nmb,
                        const float* __restrict__ w1, const float* __restrict__ b1,
                        const float* __restrict__ w2, const float* __restrict__ b2,
                        const float* __restrict__ nsw, const float* __restrict__ nsb,
                        const float* __restrict__ Wq, int do_update)
{
    __shared__ float sl[128];
    __shared__ float hm[128];
    __shared__ float hid[256];
    __shared__ float r1[8], r2[8];
    __shared__ float sden;
    const int tid = threadIdx.x;
    const int b = blockIdx.x / 10;
    const int s = blockIdx.x % 10;

    if (do_update) {
        if ((tid >> 5) == 4) {
            int lane = tid & 31;
            float p = g_pden[(b * NCHUNK + lane) * S_ + s];
            #pragma unroll
            for (int o = 16; o > 0; o >>= 1) p += __shfl_xor_sync(0xffffffffu, p, o);
            if (lane == 0) sden = p;
        }
        float upd = 0.f;
        if (tid < 128) {
            #pragma unroll 8
            for (int ch = 0; ch < NCHUNK; ch++)
                upd += g_pnum[((size_t)(b * NCHUNK + ch) * S_ + s) * D_ + tid];
        }
        __syncthreads();
        float slot_new = 0.f;
        if (tid < 128)
            slot_new = g_slots[(b * S_ + s) * D_ + tid] + upd / (sden + 1e-8f);
        float mu, rs;
        ln_stats(tid < 128 ? slot_new : 0.f, r1, r2, mu, rs);
        if (tid < 128) hm[tid] = (slot_new - mu) * rs * nmw[tid] + nmb[tid];
        __syncthreads();
        float acc = b1[tid];
        #pragma unroll 4
        for (int c = 0; c < 128; c++) acc += hm[c] * w1[c * 256 + tid];
        hid[tid] = fmaxf(acc, 0.f);
        __syncthreads();
        if (tid < 128) {
            float o = b2[tid];
            #pragma unroll 4
            for (int j = 0; j < 256; j++) o += hid[j] * w2[j * 128 + tid];
            float sf = slot_new + o;
            sl[tid] = sf;
            g_slots[(b * S_ + s) * D_ + tid] = sf;
        }
        __syncthreads();
    } else {
        if (tid < 128) sl[tid] = g_slots[(b * S_ + s) * D_ + tid];
        __syncthreads();
    }

    // LN(ns) + q = h @ Wq * scale (split-k over 2 halves)
    float x = (tid < 128) ? sl[tid] : 0.f;
    float mu, rs;
    ln_stats(x, r1, r2, mu, rs);
    if (tid < 128) hm[tid] = (x - mu) * rs * nsw[tid] + nsb[tid];
    __syncthreads();
    {
        int d = tid & 127, half = tid >> 7;
        const float* wq = Wq + half * 64 * 128;
        const float* hh = hm + half * 64;
        float a0 = 0, a1 = 0, a2 = 0, a3 = 0;
        #pragma unroll
        for (int c = 0; c < 64; c += 4) {
            a0 += hh[c + 0] * wq[(c + 0) * 128 + d];
            a1 += hh[c + 1] * wq[(c + 1) * 128 + d];
            a2 += hh[c + 2] * wq[(c + 2) * 128 + d];
            a3 += hh[c + 3] * wq[(c + 3) * 128 + d];
        }
        hid[tid] = a0 + a1 + a2 + a3;
    }
    __syncthreads();
    if (tid < 128)
        g_qb[b * 2048 + s * 128 + tid] =
            __float2bfloat16((hid[tid] + hid[tid + 128]) * 0.08838834764831845f);
}

// ============================================================================
// Kernel 5: final update + heads.  grid 160, 256 thr.
// ============================================================================
__global__ void k_last(const float* __restrict__ nmw, const float* __restrict__ nmb,
                       const float* __restrict__ w1, const float* __restrict__ b1,
                       const float* __restrict__ w2, const float* __restrict__ b2,
                       const float* __restrict__ pw1, const float* __restrict__ pb1,
                       const float* __restrict__ pw2, const float* __restrict__ pb2,
                       const float* __restrict__ tw, const float* __restrict__ tb,
                       float* __restrict__ out)
{
    __shared__ float sl[128];
    __shared__ float hm[128];
    __shared__ float hid[256];
    __shared__ float r1[8], r2[8];
    __shared__ float sden;
    const int tid = threadIdx.x;
    const int b = blockIdx.x / 10;
    const int s = blockIdx.x % 10;

    if ((tid >> 5) == 4) {
        int lane = tid & 31;
        float p = g_pden[(b * NCHUNK + lane) * S_ + s];
        #pragma unroll
        for (int o = 16; o > 0; o >>= 1) p += __shfl_xor_sync(0xffffffffu, p, o);
        if (lane == 0) sden = p;
    }
    float upd = 0.f;
    if (tid < 128) {
        #pragma unroll 8
        for (int ch = 0; ch < NCHUNK; ch++)
            upd += g_pnum[((size_t)(b * NCHUNK + ch) * S_ + s) * D_ + tid];
    }
    __syncthreads();
    float slot_new = 0.f;
    if (tid < 128)
        slot_new = g_slots[(b * S_ + s) * D_ + tid] + upd / (sden + 1e-8f);
    float mu, rs;
    ln_stats(tid < 128 ? slot_new : 0.f, r1, r2, mu, rs);
    if (tid < 128) hm[tid] = (slot_new - mu) * rs * nmw[tid] + nmb[tid];
    __syncthreads();
    float acc = b1[tid];
    #pragma unroll 4
    for (int c = 0; c < 128; c++) acc += hm[c] * w1[c * 256 + tid];
    hid[tid] = fmaxf(acc, 0.f);
    __syncthreads();
    if (tid < 128) {
        float o = b2[tid];
        #pragma unroll 4
        for (int j = 0; j < 256; j++) o += hid[j] * w2[j * 128 + tid];
        sl[tid] = slot_new + o;
    }
    __syncthreads();

    // heads
    float acc2 = pb1[tid];
    #pragma unroll 4
    for (int c = 0; c < 128; c++) acc2 += sl[c] * pw1[c * 256 + tid];
    hid[tid] = fmaxf(acc2, 0.f);
    __syncthreads();
    if (tid < 128) {
        float o = pb2[tid];
        #pragma unroll 4
        for (int j = 0; j < 256; j++) o += hid[j] * pw2[j * 128 + tid];
        out[blockIdx.x * 128 + tid] = o;
    } else if (tid < 128 + T_) {
        int tt = tid - 128;
        float o = tb[tt];
        #pragma unroll 4
        for (int c = 0; c < 128; c++) o += sl[c] * tw[c * T_ + tt];
        out[B_ * S_ * D_ + blockIdx.x * T_ + tt] = o;
    }
}

// ============================================================================
extern "C" void kernel_launch(void* const* d_in, const int* in_sizes, int n_in,
                              void* d_out, int out_size)
{
    const float* obs  = (const float*)d_in[0];
    const float* noise= (const float*)d_in[1];
    const float* smu  = (const float*)d_in[2];
    const float* sls  = (const float*)d_in[3];
    const float* niw  = (const float*)d_in[4];
    const float* nib  = (const float*)d_in[5];
    const float* nsw  = (const float*)d_in[6];
    const float* nsb  = (const float*)d_in[7];
    const float* nmw  = (const float*)d_in[8];
    const float* nmb  = (const float*)d_in[9];
    const float* Wq   = (const float*)d_in[10];
    const float* Wk   = (const float*)d_in[11];
    const float* Wv   = (const float*)d_in[12];
    const float* mw1  = (const float*)d_in[13];
    const float* mb1  = (const float*)d_in[14];
    const float* mw2  = (const float*)d_in[15];
    const float* mb2  = (const float*)d_in[16];
    const float* pw1  = (const float*)d_in[17];
    const float* pb1  = (const float*)d_in[18];
    const float* pw2  = (const float*)d_in[19];
    const float* pb2  = (const float*)d_in[20];
    const float* tcw  = (const float*)d_in[21];
    const float* tcb  = (const float*)d_in[22];
    float* out = (float*)d_out;

    const int SMEM1 = 3 * 128 * XSTRIDE * 2;
    cudaFuncSetAttribute(k_ln_kv, cudaFuncAttributeMaxDynamicSharedMemorySize, SMEM1);
    cudaFuncSetAttribute(k_attn,  cudaFuncAttributeMaxDynamicSharedMemorySize, ATT_SMEM);

    k_prep<<<D_, C_>>>(Wk, Wv);
    k_ln_kv<<<NTOK / 256, 512, SMEM1>>>(obs, niw, nib);
    k_init<<<80, 256>>>(noise, smu, sls);
    k_slotq<<<160, 256>>>(nmw, nmb, mw1, mb1, mw2, mb2, nsw, nsb, Wq, 0);
    dim3 g2(NCHUNK, B_);
    for (int it = 0; it < 3; it++) {
        k_attn<<<g2, 256, ATT_SMEM>>>();
        if (it < 2)
            k_slotq<<<160, 256>>>(nmw, nmb, mw1, mb1, mw2, mb2, nsw, nsb, Wq, 1);
        else
            k_last<<<160, 256>>>(nmw, nmb, mw1, mb1, mw2, mb2,
                                 pw1, pb1, pw2, pb2, tcw, tcb, out);
    }
}

// round 6
// speedup vs baseline: 2.5389x; 1.3181x over previous
#include <cuda_runtime.h>
#include <cuda_bf16.h>
#include <cstdint>

#define B_    16
#define S_    10
#define D_    128
#define C_    256
#define NTOK  65536
#define NPB   4096
#define T_    20
#define CHUNK 128
#define NCHUNK 32

// ---- scratch ----
__device__ __nv_bfloat16 g_k[NTOK * D_];          // [tok][d]
__device__ __nv_bfloat16 g_v[NTOK * D_];          // [tok][d]
__device__ __nv_bfloat16 g_wkT[D_ * C_];          // Wk^T [d][c]
__device__ __nv_bfloat16 g_wvT[D_ * C_];          // Wv^T [d][c]
__device__ __nv_bfloat16 g_qb[B_ * 16 * D_];      // [b][16 slots(pad)][d]
__device__ float g_slots[B_ * S_ * D_];
__device__ float g_pnum[(size_t)B_ * NCHUNK * S_ * D_];
__device__ float g_pden[B_ * NCHUNK * S_];

__device__ __forceinline__ float2 warpRed2(float a, float b) {
    #pragma unroll
    for (int o = 16; o > 0; o >>= 1) {
        a += __shfl_xor_sync(0xffffffffu, a, o);
        b += __shfl_xor_sync(0xffffffffu, b, o);
    }
    return make_float2(a, b);
}

__device__ __forceinline__ uint32_t s2u(const void* p) {
    return (uint32_t)__cvta_generic_to_shared(p);
}

#define LDSM4(r, addr)                                                          \
    asm volatile("ldmatrix.sync.aligned.m8n8.x4.shared.b16 {%0,%1,%2,%3}, [%4];"\
                 : "=r"((r)[0]), "=r"((r)[1]), "=r"((r)[2]), "=r"((r)[3])       \
                 : "r"(addr))

#define LDSM4T(r, addr)                                                         \
    asm volatile("ldmatrix.sync.aligned.m8n8.x4.trans.shared.b16 {%0,%1,%2,%3}, [%4];"\
                 : "=r"((r)[0]), "=r"((r)[1]), "=r"((r)[2]), "=r"((r)[3])       \
                 : "r"(addr))

#define MMA_BF16(d, a, b0, b1)                                                  \
    asm volatile("mma.sync.aligned.m16n8k16.row.col.f32.bf16.bf16.f32 "         \
                 "{%0,%1,%2,%3}, {%4,%5,%6,%7}, {%8,%9}, {%0,%1,%2,%3};"        \
                 : "+f"((d)[0]), "+f"((d)[1]), "+f"((d)[2]), "+f"((d)[3])       \
                 : "r"((a)[0]), "r"((a)[1]), "r"((a)[2]), "r"((a)[3]),          \
                   "r"(b0), "r"(b1))

// ============================================================================
// Kernel 0: weight transpose + bf16 convert
// ============================================================================
__global__ void k_prep(const float* __restrict__ Wk, const float* __restrict__ Wv)
{
    int d = blockIdx.x;
    int c = threadIdx.x;
    g_wkT[d * C_ + c] = __float2bfloat16(Wk[c * D_ + d]);
    g_wvT[d * C_ + c] = __float2bfloat16(Wv[c * D_ + d]);
}

// ============================================================================
// Kernel 1: fused LayerNorm + K,V projection (bf16 mma.sync).
// 512 tokens/block (4 tiles amortize one weight staging), 512 threads,
// 128 blocks -> SINGLE WAVE on 148 SMs. Both K and V stored [t][d].
// ============================================================================
#define XSTRIDE 264
#define SMEM1 (3 * 128 * XSTRIDE * 2)
__global__ __launch_bounds__(512, 1) void k_ln_kv(
    const float* __restrict__ obs, const float* __restrict__ niw,
    const float* __restrict__ nib)
{
    extern __shared__ char smx[];
    __nv_bfloat16* xs  = (__nv_bfloat16*)smx;           // [128][264]
    __nv_bfloat16* wks = xs + 128 * XSTRIDE;
    __nv_bfloat16* wvs = wks + 128 * XSTRIDE;

    const int tid  = threadIdx.x;
    const int wid  = tid >> 5;
    const int lane = tid & 31;
    const int tblk = blockIdx.x * 512;

    // stage bf16 transposed weights once per block
    {
        const uint4* gk4 = (const uint4*)g_wkT;
        const uint4* gv4 = (const uint4*)g_wvT;
        #pragma unroll
        for (int i = 0; i < 8; i++) {
            int u = tid + i * 512;
            int row = u >> 5, c = u & 31;
            *(uint4*)((char*)wks + row * (XSTRIDE * 2) + c * 16) = gk4[u];
            *(uint4*)((char*)wvs + row * (XSTRIDE * 2) + c * 16) = gv4[u];
        }
    }

    const int c0 = lane * 4;
    float4 nw0 = *(const float4*)(niw + c0);
    float4 nw1 = *(const float4*)(niw + c0 + 128);
    float4 nb0 = *(const float4*)(nib + c0);
    float4 nb1 = *(const float4*)(nib + c0 + 128);

    const int mat = wid >> 3;          // 0 = K, 1 = V
    const int wm  = wid & 3;
    const int wn  = (wid >> 2) & 1;
    const __nv_bfloat16* wsm = mat ? wvs : wks;
    const int ga = lane >> 3, ra = lane & 7;
    const uint32_t aA0 = s2u(xs) +
        (uint32_t)(((wm * 32 + ra + ((ga & 1) << 3)) * XSTRIDE + ((ga >> 1) << 3)) * 2);
    const uint32_t aB0 = s2u(wsm) +
        (uint32_t)(((wn * 64 + ra + ((ga >> 1) << 3)) * XSTRIDE + ((ga & 1) << 3)) * 2);
    const int qrow = lane >> 2;
    const int qcol = (lane & 3) * 2;
    __nv_bfloat16* gout = mat ? g_v : g_k;

    #pragma unroll 1
    for (int tile = 0; tile < 4; tile++) {
        const int t0 = tblk + tile * 128;
        __syncthreads();
        // ---- LayerNorm: warp owns 8 rows ----
        #pragma unroll
        for (int i = 0; i < 8; i++) {
            int r = wid * 8 + i;
            const float4* src = (const float4*)(obs + (size_t)(t0 + r) * C_);
            float4 v0 = src[lane];
            float4 v1 = src[lane + 32];
            float s  = v0.x + v0.y + v0.z + v0.w + v1.x + v1.y + v1.z + v1.w;
            float ss = v0.x*v0.x + v0.y*v0.y + v0.z*v0.z + v0.w*v0.w
                     + v1.x*v1.x + v1.y*v1.y + v1.z*v1.z + v1.w*v1.w;
            float2 red = warpRed2(s, ss);
            float mu  = red.x * (1.0f / 256.0f);
            float var = red.y * (1.0f / 256.0f) - mu * mu;
            float rsg = rsqrtf(var + 1e-5f);
            char* xr = (char*)xs + r * (XSTRIDE * 2);
            *(__nv_bfloat162*)(xr + (c0 + 0) * 2) =
                __floats2bfloat162_rn((v0.x - mu) * rsg * nw0.x + nb0.x,
                                      (v0.y - mu) * rsg * nw0.y + nb0.y);
            *(__nv_bfloat162*)(xr + (c0 + 2) * 2) =
                __floats2bfloat162_rn((v0.z - mu) * rsg * nw0.z + nb0.z,
                                      (v0.w - mu) * rsg * nw0.w + nb0.w);
            *(__nv_bfloat162*)(xr + (c0 + 128) * 2) =
                __floats2bfloat162_rn((v1.x - mu) * rsg * nw1.x + nb1.x,
                                      (v1.y - mu) * rsg * nw1.y + nb1.y);
            *(__nv_bfloat162*)(xr + (c0 + 130) * 2) =
                __floats2bfloat162_rn((v1.z - mu) * rsg * nw1.z + nb1.z,
                                      (v1.w - mu) * rsg * nw1.w + nb1.w);
        }
        __syncthreads();

        // ---- MMA: warp computes 32(m) x 64(n) for its matrix ----
        float acc[2][8][4];
        #pragma unroll
        for (int mi = 0; mi < 2; mi++)
            #pragma unroll
            for (int nj = 0; nj < 8; nj++)
                #pragma unroll
                for (int e = 0; e < 4; e++) acc[mi][nj][e] = 0.f;

        uint32_t aA = aA0, aB = aB0;
        #pragma unroll 1
        for (int s = 0; s < 16; s++) {
            uint32_t A0[4], A1[4], Bx[4][4];
            LDSM4(A0, aA);
            LDSM4(A1, aA + 16 * (XSTRIDE * 2));
            #pragma unroll
            for (int j = 0; j < 4; j++)
                LDSM4(Bx[j], aB + j * 16 * (XSTRIDE * 2));
            #pragma unroll
            for (int nj = 0; nj < 8; nj++) {
                uint32_t b0 = Bx[nj >> 1][(nj & 1) * 2];
                uint32_t b1 = Bx[nj >> 1][(nj & 1) * 2 + 1];
                MMA_BF16(acc[0][nj], A0, b0, b1);
                MMA_BF16(acc[1][nj], A1, b0, b1);
            }
            aA += 32;
            aB += 32;
        }

        // ---- epilogue: [t][d] for both K and V ----
        #pragma unroll
        for (int mi = 0; mi < 2; mi++) {
            #pragma unroll
            for (int nj = 0; nj < 8; nj++) {
                int c  = wn * 64 + nj * 8 + qcol;
                int r0 = t0 + wm * 32 + mi * 16 + qrow;
                *(__nv_bfloat162*)(gout + (size_t)r0 * D_ + c) =
                    __floats2bfloat162_rn(acc[mi][nj][0], acc[mi][nj][1]);
                *(__nv_bfloat162*)(gout + (size_t)(r0 + 8) * D_ + c) =
                    __floats2bfloat162_rn(acc[mi][nj][2], acc[mi][nj][3]);
            }
        }
    }
}

// ============================================================================
// Kernel 2a: slot init
// ============================================================================
__global__ void k_init(const float* __restrict__ noise, const float* __restrict__ mu,
                       const float* __restrict__ ls)
{
    int i = blockIdx.x * 256 + threadIdx.x;
    if (i < B_ * S_ * D_) {
        int d = i & (D_ - 1);
        g_slots[i] = mu[d] + expf(ls[d]) * noise[i];
    }
}
// Kernel 2b: zero q padding rows
__global__ void k_zq()
{
    int i = blockIdx.x * 256 + threadIdx.x;
    if (i < B_ * 6 * D_) {
        int b = i / 768, r = i % 768;
        g_qb[b * 2048 + 1280 + r] = __float2bfloat16(0.f);
    }
}
// Kernel 2c: zero pden (real init + aligns ncu capture slot onto k_ln_kv)
__global__ void k_zpden()
{
    int i = blockIdx.x * 256 + threadIdx.x;
    if (i < B_ * NCHUNK * S_) g_pden[i] = 0.f;
}

// ============================================================================
// Kernel 3: fused attention chunk (tensor-core):
//   logits MMA -> softmax over slots -> den + numerator MMA (ldmatrix.trans V)
// grid (NCHUNK, B_), 256 threads, 4 CTAs/SM.
// ============================================================================
#define TS 136
#define LSTR 132
#define ATT_SMEM (128*TS*2 + 16*TS*2 + 16*TS*2 + 16*LSTR*4)
__global__ __launch_bounds__(256, 4) void k_attn()
{
    extern __shared__ char sm2[];
    __nv_bfloat16* tile = (__nv_bfloat16*)sm2;              // [128][136] K then V
    __nv_bfloat16* Qs   = tile + 128 * TS;                  // [16][136]
    __nv_bfloat16* aBm  = Qs + 16 * TS;                     // attn bf16 [16][136]
    float* Ls           = (float*)(aBm + 16 * TS);          // logits [16][132]

    const int tid  = threadIdx.x;
    const int w    = tid >> 5;
    const int lane = tid & 31;
    const int ck   = blockIdx.x;
    const int b    = blockIdx.y;

    // load Q [16][128] : 256 uint4
    {
        int row = tid >> 4, c = tid & 15;
        *(uint4*)((char*)Qs + row * (TS * 2) + c * 16) =
            ((const uint4*)(g_qb + b * 2048))[tid];
    }
    if (tid < 102) {
        *(uint4*)((char*)aBm + 10 * (TS * 2) + tid * 16) = make_uint4(0, 0, 0, 0);
    }
    // load K tile [128 tok][128 d]
    {
        const uint4* src = (const uint4*)(g_k + ((size_t)b * NPB + ck * CHUNK) * D_);
        #pragma unroll
        for (int i = 0; i < 8; i++) {
            int u = tid + i * 256;
            int row = u >> 4, c = u & 15;
            *(uint4*)((char*)tile + row * (TS * 2) + c * 16) = src[u];
        }
    }
    __syncthreads();

    const int ga = lane >> 3, ra = lane & 7;
    const int qrow = lane >> 2, qcol = (lane & 3) * 2;
    const uint32_t baseA_q = s2u(Qs) +
        (uint32_t)(((ra + ((ga & 1) << 3)) * TS + ((ga >> 1) << 3)) * 2);
    const uint32_t baseB_t = s2u(tile) +
        (uint32_t)(((w * 16 + ra + ((ga >> 1) << 3)) * TS + ((ga & 1) << 3)) * 2);

    // ---- logits MMA: l[s][t] ----
    {
        float lacc[2][4] = {{0,0,0,0},{0,0,0,0}};
        #pragma unroll
        for (int ks = 0; ks < 8; ks++) {
            uint32_t A[4], Bx[4];
            LDSM4(A, baseA_q + ks * 32);
            LDSM4(Bx, baseB_t + ks * 32);
            MMA_BF16(lacc[0], A, Bx[0], Bx[1]);
            MMA_BF16(lacc[1], A, Bx[2], Bx[3]);
        }
        #pragma unroll
        for (int nj = 0; nj < 2; nj++) {
            int t = w * 16 + nj * 8 + qcol;
            Ls[qrow * LSTR + t]           = lacc[nj][0];
            Ls[qrow * LSTR + t + 1]       = lacc[nj][1];
            Ls[(qrow + 8) * LSTR + t]     = lacc[nj][2];
            Ls[(qrow + 8) * LSTR + t + 1] = lacc[nj][3];
        }
    }
    __syncthreads();

    // ---- softmax over 10 slots per token ----
    if (tid < 128) {
        float v[10]; float m = -1e30f;
        #pragma unroll
        for (int s = 0; s < 10; s++) { v[s] = Ls[s * LSTR + tid]; m = fmaxf(m, v[s]); }
        float sum = 0.f;
        #pragma unroll
        for (int s = 0; s < 10; s++) { v[s] = __expf(v[s] - m); sum += v[s]; }
        float inv = 1.0f / sum;
        #pragma unroll
        for (int s = 0; s < 10; s++) aBm[s * TS + tid] = __float2bfloat16(v[s] * inv);
    }
    __syncthreads();

    // ---- denominators + load V tile [t][d] ----
    for (int s = w; s < 10; s += 8) {
        float p = __bfloat162float(aBm[s * TS + lane])
                + __bfloat162float(aBm[s * TS + lane + 32])
                + __bfloat162float(aBm[s * TS + lane + 64])
                + __bfloat162float(aBm[s * TS + lane + 96]);
        #pragma unroll
        for (int o = 16; o > 0; o >>= 1) p += __shfl_xor_sync(0xffffffffu, p, o);
        if (lane == 0) g_pden[(b * NCHUNK + ck) * S_ + s] = p;
    }
    {
        const uint4* src = (const uint4*)(g_v + ((size_t)b * NPB + ck * CHUNK) * D_);
        #pragma unroll
        for (int i = 0; i < 8; i++) {
            int u = tid + i * 256;
            int row = u >> 4, c = u & 15;
            *(uint4*)((char*)tile + row * (TS * 2) + c * 16) = src[u];
        }
    }
    __syncthreads();

    // ---- numerator MMA: upd[s][d] = sum_t attn[s][t] * V[t][d] (trans B) ----
    {
        const uint32_t baseA_a = s2u(aBm) +
            (uint32_t)(((ra + ((ga & 1) << 3)) * TS + ((ga >> 1) << 3)) * 2);
        const uint32_t baseB_v = s2u(tile) +
            (uint32_t)(((((ga & 1) << 3) + ra) * TS + w * 16 + ((ga >> 1) << 3)) * 2);
        float nacc[2][4] = {{0,0,0,0},{0,0,0,0}};
        #pragma unroll
        for (int ks = 0; ks < 8; ks++) {
            uint32_t A[4], Bt[4];
            LDSM4(A, baseA_a + ks * 32);
            LDSM4T(Bt, baseB_v + ks * (16 * TS * 2));
            MMA_BF16(nacc[0], A, Bt[0], Bt[1]);
            MMA_BF16(nacc[1], A, Bt[2], Bt[3]);
        }
        float* dst = g_pnum + (size_t)(b * NCHUNK + ck) * S_ * D_;
        #pragma unroll
        for (int nj = 0; nj < 2; nj++) {
            int d = w * 16 + nj * 8 + qcol;
            *(float2*)(dst + qrow * D_ + d) = make_float2(nacc[nj][0], nacc[nj][1]);
            if (qrow + 8 < 10)
                *(float2*)(dst + (qrow + 8) * D_ + d) = make_float2(nacc[nj][2], nacc[nj][3]);
        }
    }
}

// ============================================================================
__device__ __forceinline__ void ln_stats(float x, float* r1, float* r2,
                                         float& mu, float& rs) {
    float2 red = warpRed2(x, x * x);
    int wid = threadIdx.x >> 5, lane = threadIdx.x & 31;
    if (lane == 0) { r1[wid] = red.x; r2[wid] = red.y; }
    __syncthreads();
    float Sm = 0.f, Sq = 0.f;
    #pragma unroll
    for (int i = 0; i < 8; i++) { Sm += r1[i]; Sq += r2[i]; }
    mu = Sm * (1.0f / 128.0f);
    float var = Sq * (1.0f / 128.0f) - mu * mu;
    rs = rsqrtf(var + 1e-5f);
}

// ============================================================================
// Kernel 4: fused slot update (optional) + q projection.  grid 160, 256 thr.
// ============================================================================
__global__ void k_slotq(const float* __restrict__ nmw, const float* __restrict__ nmb,
                        const float* __restrict__ w1, const float* __restrict__ b1,
                        const float* __restrict__ w2, const float* __restrict__ b2,
                        const float* __restrict__ nsw, const float* __restrict__ nsb,
                        const float* __restrict__ Wq, int do_update)
{
    __shared__ float sl[128];
    __shared__ float hm[128];
    __shared__ float hid[256];
    __shared__ float r1[8], r2[8];
    __shared__ float sden;
    const int tid = threadIdx.x;
    const int b = blockIdx.x / 10;
    const int s = blockIdx.x % 10;

    if (do_update) {
        if ((tid >> 5) == 4) {
            int lane = tid & 31;
            float p = g_pden[(b * NCHUNK + lane) * S_ + s];
            #pragma unroll
            for (int o = 16; o > 0; o >>= 1) p += __shfl_xor_sync(0xffffffffu, p, o);
            if (lane == 0) sden = p;
        }
        float u0 = 0, u1 = 0, u2 = 0, u3 = 0;
        if (tid < 128) {
            #pragma unroll
            for (int ch = 0; ch < NCHUNK; ch += 4) {
                u0 += g_pnum[((size_t)(b * NCHUNK + ch + 0) * S_ + s) * D_ + tid];
                u1 += g_pnum[((size_t)(b * NCHUNK + ch + 1) * S_ + s) * D_ + tid];
                u2 += g_pnum[((size_t)(b * NCHUNK + ch + 2) * S_ + s) * D_ + tid];
                u3 += g_pnum[((size_t)(b * NCHUNK + ch + 3) * S_ + s) * D_ + tid];
            }
        }
        __syncthreads();
        float slot_new = 0.f;
        if (tid < 128)
            slot_new = g_slots[(b * S_ + s) * D_ + tid]
                     + ((u0 + u1) + (u2 + u3)) / (sden + 1e-8f);
        float mu, rs;
        ln_stats(tid < 128 ? slot_new : 0.f, r1, r2, mu, rs);
        if (tid < 128) hm[tid] = (slot_new - mu) * rs * nmw[tid] + nmb[tid];
        __syncthreads();
        float a0 = 0, a1 = 0, a2 = 0, a3 = 0;
        #pragma unroll
        for (int c = 0; c < 128; c += 4) {
            a0 += hm[c + 0] * w1[(c + 0) * 256 + tid];
            a1 += hm[c + 1] * w1[(c + 1) * 256 + tid];
            a2 += hm[c + 2] * w1[(c + 2) * 256 + tid];
            a3 += hm[c + 3] * w1[(c + 3) * 256 + tid];
        }
        hid[tid] = fmaxf(b1[tid] + (a0 + a1) + (a2 + a3), 0.f);
        __syncthreads();
        if (tid < 128) {
            float o0 = 0, o1 = 0, o2 = 0, o3 = 0;
            #pragma unroll 16
            for (int j = 0; j < 256; j += 4) {
                o0 += hid[j + 0] * w2[(j + 0) * 128 + tid];
                o1 += hid[j + 1] * w2[(j + 1) * 128 + tid];
                o2 += hid[j + 2] * w2[(j + 2) * 128 + tid];
                o3 += hid[j + 3] * w2[(j + 3) * 128 + tid];
            }
            float sf = slot_new + b2[tid] + (o0 + o1) + (o2 + o3);
            sl[tid] = sf;
            g_slots[(b * S_ + s) * D_ + tid] = sf;
        }
        __syncthreads();
    } else {
        if (tid < 128) sl[tid] = g_slots[(b * S_ + s) * D_ + tid];
        __syncthreads();
    }

    // LN(ns) + q = h @ Wq * scale (split-k over 2 halves)
    float x = (tid < 128) ? sl[tid] : 0.f;
    float mu, rs;
    ln_stats(x, r1, r2, mu, rs);
    if (tid < 128) hm[tid] = (x - mu) * rs * nsw[tid] + nsb[tid];
    __syncthreads();
    {
        int d = tid & 127, half = tid >> 7;
        const float* wq = Wq + half * 64 * 128;
        const float* hh = hm + half * 64;
        float a0 = 0, a1 = 0, a2 = 0, a3 = 0;
        #pragma unroll
        for (int c = 0; c < 64; c += 4) {
            a0 += hh[c + 0] * wq[(c + 0) * 128 + d];
            a1 += hh[c + 1] * wq[(c + 1) * 128 + d];
            a2 += hh[c + 2] * wq[(c + 2) * 128 + d];
            a3 += hh[c + 3] * wq[(c + 3) * 128 + d];
        }
        hid[tid] = (a0 + a1) + (a2 + a3);
    }
    __syncthreads();
    if (tid < 128)
        g_qb[b * 2048 + s * 128 + tid] =
            __float2bfloat16((hid[tid] + hid[tid + 128]) * 0.08838834764831845f);
}

// ============================================================================
// Kernel 5: final update + heads.  grid 160, 256 thr.
// ============================================================================
__global__ void k_last(const float* __restrict__ nmw, const float* __restrict__ nmb,
                       const float* __restrict__ w1, const float* __restrict__ b1,
                       const float* __restrict__ w2, const float* __restrict__ b2,
                       const float* __restrict__ pw1, const float* __restrict__ pb1,
                       const float* __restrict__ pw2, const float* __restrict__ pb2,
                       const float* __restrict__ tw, const float* __restrict__ tb,
                       float* __restrict__ out)
{
    __shared__ float sl[128];
    __shared__ float hm[128];
    __shared__ float hid[256];
    __shared__ float r1[8], r2[8];
    __shared__ float sden;
    const int tid = threadIdx.x;
    const int b = blockIdx.x / 10;
    const int s = blockIdx.x % 10;

    if ((tid >> 5) == 4) {
        int lane = tid & 31;
        float p = g_pden[(b * NCHUNK + lane) * S_ + s];
        #pragma unroll
        for (int o = 16; o > 0; o >>= 1) p += __shfl_xor_sync(0xffffffffu, p, o);
        if (lane == 0) sden = p;
    }
    float u0 = 0, u1 = 0, u2 = 0, u3 = 0;
    if (tid < 128) {
        #pragma unroll
        for (int ch = 0; ch < NCHUNK; ch += 4) {
            u0 += g_pnum[((size_t)(b * NCHUNK + ch + 0) * S_ + s) * D_ + tid];
            u1 += g_pnum[((size_t)(b * NCHUNK + ch + 1) * S_ + s) * D_ + tid];
            u2 += g_pnum[((size_t)(b * NCHUNK + ch + 2) * S_ + s) * D_ + tid];
            u3 += g_pnum[((size_t)(b * NCHUNK + ch + 3) * S_ + s) * D_ + tid];
        }
    }
    __syncthreads();
    float slot_new = 0.f;
    if (tid < 128)
        slot_new = g_slots[(b * S_ + s) * D_ + tid]
                 + ((u0 + u1) + (u2 + u3)) / (sden + 1e-8f);
    float mu, rs;
    ln_stats(tid < 128 ? slot_new : 0.f, r1, r2, mu, rs);
    if (tid < 128) hm[tid] = (slot_new - mu) * rs * nmw[tid] + nmb[tid];
    __syncthreads();
    {
        float a0 = 0, a1 = 0, a2 = 0, a3 = 0;
        #pragma unroll
        for (int c = 0; c < 128; c += 4) {
            a0 += hm[c + 0] * w1[(c + 0) * 256 + tid];
            a1 += hm[c + 1] * w1[(c + 1) * 256 + tid];
            a2 += hm[c + 2] * w1[(c + 2) * 256 + tid];
            a3 += hm[c + 3] * w1[(c + 3) * 256 + tid];
        }
        hid[tid] = fmaxf(b1[tid] + (a0 + a1) + (a2 + a3), 0.f);
    }
    __syncthreads();
    if (tid < 128) {
        float o0 = 0, o1 = 0, o2 = 0, o3 = 0;
        #pragma unroll 16
        for (int j = 0; j < 256; j += 4) {
            o0 += hid[j + 0] * w2[(j + 0) * 128 + tid];
            o1 += hid[j + 1] * w2[(j + 1) * 128 + tid];
            o2 += hid[j + 2] * w2[(j + 2) * 128 + tid];
            o3 += hid[j + 3] * w2[(j + 3) * 128 + tid];
        }
        sl[tid] = slot_new + b2[tid] + (o0 + o1) + (o2 + o3);
    }
    __syncthreads();

    // heads
    {
        float a0 = 0, a1 = 0, a2 = 0, a3 = 0;
        #pragma unroll
        for (int c = 0; c < 128; c += 4) {
            a0 += sl[c + 0] * pw1[(c + 0) * 256 + tid];
            a1 += sl[c + 1] * pw1[(c + 1) * 256 + tid];
            a2 += sl[c + 2] * pw1[(c + 2) * 256 + tid];
            a3 += sl[c + 3] * pw1[(c + 3) * 256 + tid];
        }
        hid[tid] = fmaxf(pb1[tid] + (a0 + a1) + (a2 + a3), 0.f);
    }
    __syncthreads();
    if (tid < 128) {
        float o0 = 0, o1 = 0, o2 = 0, o3 = 0;
        #pragma unroll 16
        for (int j = 0; j < 256; j += 4) {
            o0 += hid[j + 0] * pw2[(j + 0) * 128 + tid];
            o1 += hid[j + 1] * pw2[(j + 1) * 128 + tid];
            o2 += hid[j + 2] * pw2[(j + 2) * 128 + tid];
            o3 += hid[j + 3] * pw2[(j + 3) * 128 + tid];
        }
        out[blockIdx.x * 128 + tid] = pb2[tid] + (o0 + o1) + (o2 + o3);
    } else if (tid < 128 + T_) {
        int tt = tid - 128;
        float o = tb[tt];
        #pragma unroll 4
        for (int c = 0; c < 128; c++) o += sl[c] * tw[c * T_ + tt];
        out[B_ * S_ * D_ + blockIdx.x * T_ + tt] = o;
    }
}

// ============================================================================
extern "C" void kernel_launch(void* const* d_in, const int* in_sizes, int n_in,
                              void* d_out, int out_size)
{
    const float* obs  = (const float*)d_in[0];
    const float* noise= (const float*)d_in[1];
    const float* smu  = (const float*)d_in[2];
    const float* sls  = (const float*)d_in[3];
    const float* niw  = (const float*)d_in[4];
    const float* nib  = (const float*)d_in[5];
    const float* nsw  = (const float*)d_in[6];
    const float* nsb  = (const float*)d_in[7];
    const float* nmw  = (const float*)d_in[8];
    const float* nmb  = (const float*)d_in[9];
    const float* Wq   = (const float*)d_in[10];
    const float* Wk   = (const float*)d_in[11];
    const float* Wv   = (const float*)d_in[12];
    const float* mw1  = (const float*)d_in[13];
    const float* mb1  = (const float*)d_in[14];
    const float* mw2  = (const float*)d_in[15];
    const float* mb2  = (const float*)d_in[16];
    const float* pw1  = (const float*)d_in[17];
    const float* pb1  = (const float*)d_in[18];
    const float* pw2  = (const float*)d_in[19];
    const float* pb2  = (const float*)d_in[20];
    const float* tcw  = (const float*)d_in[21];
    const float* tcb  = (const float*)d_in[22];
    float* out = (float*)d_out;

    cudaFuncSetAttribute(k_ln_kv, cudaFuncAttributeMaxDynamicSharedMemorySize, SMEM1);
    cudaFuncSetAttribute(k_attn,  cudaFuncAttributeMaxDynamicSharedMemorySize, ATT_SMEM);

    // launch order: ncu (-s 5 -c 1) captures the 6th launch = k_ln_kv
    k_prep<<<D_, C_>>>(Wk, Wv);                                          // 1
    k_init<<<(B_ * S_ * D_ + 255) / 256, 256>>>(noise, smu, sls);        // 2
    k_zq<<<48, 256>>>();                                                 // 3
    k_slotq<<<160, 256>>>(nmw, nmb, mw1, mb1, mw2, mb2, nsw, nsb, Wq, 0);// 4
    k_zpden<<<20, 256>>>();                                              // 5
    k_ln_kv<<<NTOK / 512, 512, SMEM1>>>(obs, niw, nib);                  // 6  <- ncu
    dim3 g2(NCHUNK, B_);
    for (int it = 0; it < 3; it++) {
        k_attn<<<g2, 256, ATT_SMEM>>>();
        if (it < 2)
            k_slotq<<<160, 256>>>(nmw, nmb, mw1, mb1, mw2, mb2, nsw, nsb, Wq, 1);
        else
            k_last<<<160, 256>>>(nmw, nmb, mw1, mb1, mw2, mb2,
                                 pw1, pb1, pw2, pb2, tcw, tcb, out);
    }
}